// round 13
// baseline (speedup 1.0000x reference)
#include <cuda_runtime.h>
#include <cuda_bf16.h>
#include <math_constants.h>
#include <cstdint>

// Problem constants
#define SEQ   1024
#define BATCH 8
#define EMB   1024
#define NH    16
#define HD    64
#define MROWS (SEQ*BATCH)        // 8192
#define NHEADS_TOT (BATCH*NH)    // 128

// ---------------------------------------------------------------------------
// Scratch (device globals; allocation-free)
// ---------------------------------------------------------------------------
__device__ float g_Q[NHEADS_TOT * SEQ * HD];   // [n][s][d], pre-scaled by 1/8
__device__ float g_K[NHEADS_TOT * SEQ * HD];
__device__ float g_V[NHEADS_TOT * SEQ * HD];
__device__ __nv_bfloat16 g_Xh[MROWS * EMB];
__device__ __nv_bfloat16 g_Xm[MROWS * EMB];
__device__ __nv_bfloat16 g_Wqh[3 * EMB * EMB];
__device__ __nv_bfloat16 g_Wqm[3 * EMB * EMB];
__device__ __nv_bfloat16 g_Woh[EMB * EMB];
__device__ __nv_bfloat16 g_Wom[EMB * EMB];
__device__ __nv_bfloat16 g_Ch[MROWS * EMB];    // ctx hi split, [s,b,e]
__device__ __nv_bfloat16 g_Cm[MROWS * EMB];    // ctx mid split

// ---------------------------------------------------------------------------
// Helpers (sm_103 plain: mma.sync + cp.async + ldmatrix only)
// ---------------------------------------------------------------------------
__device__ __forceinline__ uint32_t smem_u32(const void* p) {
    uint32_t a;
    asm("{ .reg .u64 t; cvta.to.shared.u64 t, %1; cvt.u32.u64 %0, t; }"
        : "=r"(a) : "l"(p));
    return a;
}

__device__ __forceinline__ void cp16(uint32_t dst, const void* src) {
    asm volatile("cp.async.cg.shared.global [%0], [%1], 16;" :: "r"(dst), "l"(src));
}

__device__ __forceinline__ uint16_t bf16_bits(float x) {
    return __bfloat16_as_ushort(__float2bfloat16(x));
}
__device__ __forceinline__ float bf16_val(float x, uint16_t& bits) {
    __nv_bfloat16 h = __float2bfloat16(x);
    bits = __bfloat16_as_ushort(h);
    return __bfloat162float(h);
}

// bf16 MMA: D += A(16x16) * B(16x8)^T
__device__ __forceinline__ void mma16(float* c, const uint32_t* a, const uint32_t* b) {
    asm volatile(
        "mma.sync.aligned.m16n8k16.row.col.f32.bf16.bf16.f32 "
        "{%0,%1,%2,%3}, {%4,%5,%6,%7}, {%8,%9}, {%0,%1,%2,%3};"
        : "+f"(c[0]), "+f"(c[1]), "+f"(c[2]), "+f"(c[3])
        : "r"(a[0]), "r"(a[1]), "r"(a[2]), "r"(a[3]), "r"(b[0]), "r"(b[1]));
}

__device__ __forceinline__ void ldsm_x4(uint32_t* r, uint32_t addr) {
    asm volatile("ldmatrix.sync.aligned.m8n8.x4.shared.b16 {%0,%1,%2,%3}, [%4];"
        : "=r"(r[0]), "=r"(r[1]), "=r"(r[2]), "=r"(r[3]) : "r"(addr));
}
__device__ __forceinline__ void ldsm_x4_t(uint32_t* r, uint32_t addr) {
    asm volatile("ldmatrix.sync.aligned.m8n8.x4.trans.shared.b16 {%0,%1,%2,%3}, [%4];"
        : "=r"(r[0]), "=r"(r[1]), "=r"(r[2]), "=r"(r[3]) : "r"(addr));
}

// float4 -> packed bf16 hi / mid uint2
__device__ __forceinline__ void split4(float4 v, uint2& h, uint2& m) {
    uint16_t hb0, hb1, hb2, hb3;
    float h0 = bf16_val(v.x, hb0);
    float h1 = bf16_val(v.y, hb1);
    float h2 = bf16_val(v.z, hb2);
    float h3 = bf16_val(v.w, hb3);
    uint16_t m0 = bf16_bits(v.x - h0), m1 = bf16_bits(v.y - h1);
    uint16_t m2 = bf16_bits(v.z - h2), m3 = bf16_bits(v.w - h3);
    h = make_uint2((uint32_t)hb0 | ((uint32_t)hb1 << 16),
                   (uint32_t)hb2 | ((uint32_t)hb3 << 16));
    m = make_uint2((uint32_t)m0 | ((uint32_t)m1 << 16),
                   (uint32_t)m2 | ((uint32_t)m3 << 16));
}

// ---------------------------------------------------------------------------
// Split kernel: x -> (hi = bf16(x), mid = bf16(x - hi)), packed 2x bf16/u32
// ---------------------------------------------------------------------------
__global__ __launch_bounds__(256) void split_bf16_kernel(
    const float4* __restrict__ src, uint2* __restrict__ hi,
    uint2* __restrict__ mid, int n4)
{
    int i = blockIdx.x * 256 + threadIdx.x;
    if (i >= n4) return;
    uint2 h, m;
    split4(src[i], h, m);
    hi[i] = h; mid[i] = m;
}

// ---------------------------------------------------------------------------
// bf16x3 GEMM via mma.sync: C = A @ B^T + bias.
// Block 128x128, BK=32, **3-stage** cp.async pipeline, 256 threads.
// 8 warps in 2(m)x4(n); warp tile 64x32 = 4x4 m16n8k16 tiles.
// Per chunk: ONE barrier; next-next load issued right after it, overlapping
// the MMA loop (it writes the stage consumed two iterations ago).
// ---------------------------------------------------------------------------
#define BKE   32
#define RS    40
#define TILE_E (128*RS)
#define TILE_B (TILE_E*2)
#define STAGE_E (4*TILE_E)
#define STAGE_B (4*TILE_B)        // 40960 bytes
#define G_STAGES 3
#define G_SMEM (G_STAGES*STAGE_B) // 122880 bytes
#define NCHUNK (1024/BKE)

template<int MODE>
__global__ __launch_bounds__(256, 1)
void tc_gemm(const __nv_bfloat16* __restrict__ Ah, const __nv_bfloat16* __restrict__ Am,
             const __nv_bfloat16* __restrict__ Bh, const __nv_bfloat16* __restrict__ Bm,
             const float* __restrict__ bias, float* __restrict__ Cout)
{
    extern __shared__ __nv_bfloat16 smbf[];
    const int tid  = threadIdx.x;
    const int wid  = tid >> 5;
    const int lane = tid & 31;
    const int m0 = blockIdx.y * 128;
    const int n0 = blockIdx.x * 128;
    const int warp_m = (wid & 1) * 64;
    const int warp_n = (wid >> 1) * 32;
    const int lr = lane >> 2;
    const int lc = lane & 3;

    float acc[4][4][4];
    #pragma unroll
    for (int mt = 0; mt < 4; mt++)
        #pragma unroll
        for (int nt = 0; nt < 4; nt++)
            #pragma unroll
            for (int r = 0; r < 4; r++) acc[mt][nt][r] = 0.0f;

    const uint32_t smb = smem_u32(smbf);

    auto load_chunk = [&](int st, int k0) {
        const uint32_t sb = smb + (uint32_t)st * STAGE_B;
        #pragma unroll
        for (int i = 0; i < 2; i++) {
            const int idx = tid + i * 256;
            const int r = idx >> 2, q = idx & 3;
            const uint32_t o = (uint32_t)r * (RS * 2) + (uint32_t)q * 16;
            const size_t ga = (size_t)(m0 + r) * 1024 + k0 + q * 8;
            const size_t gb = (size_t)(n0 + r) * 1024 + k0 + q * 8;
            cp16(sb + 0 * TILE_B + o, Ah + ga);
            cp16(sb + 1 * TILE_B + o, Am + ga);
            cp16(sb + 2 * TILE_B + o, Bh + gb);
            cp16(sb + 3 * TILE_B + o, Bm + gb);
        }
        asm volatile("cp.async.commit_group;" ::: "memory");
    };

    load_chunk(0, 0);
    load_chunk(1, BKE);

    int st = 0;      // stage of chunk c
    for (int c = 0; c < NCHUNK; c++) {
        if (c < NCHUNK - 1) asm volatile("cp.async.wait_group 1;" ::: "memory");
        else                asm volatile("cp.async.wait_group 0;" ::: "memory");
        __syncthreads();
        // Issue load for chunk c+2 into the stage consumed at iteration c-1.
        // The barrier above orders it after all warps' MMAs of c-1.
        if (c + 2 < NCHUNK) {
            int nst = st + 2; if (nst >= G_STAGES) nst -= G_STAGES;
            load_chunk(nst, (c + 2) * BKE);
        }

        const __nv_bfloat16* As_h = smbf + st * STAGE_E;
        const __nv_bfloat16* As_m = As_h + TILE_E;
        const __nv_bfloat16* Bs_h = As_h + 2 * TILE_E;
        const __nv_bfloat16* Bs_m = As_h + 3 * TILE_E;

        #pragma unroll
        for (int ks = 0; ks < 2; ks++) {
            const int kb = ks * 16 + 2 * lc;
            uint32_t ah[4][4], am[4][4], bh[4][2], bm[4][2];
            #pragma unroll
            for (int mt = 0; mt < 4; mt++) {
                const int row = warp_m + mt * 16 + lr;
                const __nv_bfloat16* ph = As_h + row * RS + kb;
                const __nv_bfloat16* pm = As_m + row * RS + kb;
                ah[mt][0] = *(const uint32_t*)(ph);
                ah[mt][1] = *(const uint32_t*)(ph + 8 * RS);
                ah[mt][2] = *(const uint32_t*)(ph + 8);
                ah[mt][3] = *(const uint32_t*)(ph + 8 * RS + 8);
                am[mt][0] = *(const uint32_t*)(pm);
                am[mt][1] = *(const uint32_t*)(pm + 8 * RS);
                am[mt][2] = *(const uint32_t*)(pm + 8);
                am[mt][3] = *(const uint32_t*)(pm + 8 * RS + 8);
            }
            #pragma unroll
            for (int nt = 0; nt < 4; nt++) {
                const int row = warp_n + nt * 8 + lr;
                const __nv_bfloat16* ph = Bs_h + row * RS + kb;
                const __nv_bfloat16* pm = Bs_m + row * RS + kb;
                bh[nt][0] = *(const uint32_t*)(ph);
                bh[nt][1] = *(const uint32_t*)(ph + 8);
                bm[nt][0] = *(const uint32_t*)(pm);
                bm[nt][1] = *(const uint32_t*)(pm + 8);
            }
            #pragma unroll
            for (int mt = 0; mt < 4; mt++)
                #pragma unroll
                for (int nt = 0; nt < 4; nt++) {
                    mma16(acc[mt][nt], ah[mt], bh[nt]);
                    mma16(acc[mt][nt], ah[mt], bm[nt]);
                    mma16(acc[mt][nt], am[mt], bh[nt]);
                }
        }
        if (++st == G_STAGES) st = 0;
    }

    #pragma unroll
    for (int mt = 0; mt < 4; mt++) {
        #pragma unroll
        for (int nt = 0; nt < 4; nt++) {
            const int gm = m0 + warp_m + mt * 16 + lr;
            const int gn = n0 + warp_n + nt * 8 + lc * 2;
            #pragma unroll
            for (int half = 0; half < 2; half++) {
                const int m = gm + half * 8;
                const float v0 = acc[mt][nt][half * 2 + 0] + __ldg(&bias[gn]);
                const float v1 = acc[mt][nt][half * 2 + 1] + __ldg(&bias[gn + 1]);
                if (MODE == 0) {
                    const int s = m >> 3;
                    const int b = m & 7;
                    const int h = gn / 192;
                    const int cc = gn - h * 192;
                    const int w = cc >> 6;           // 0=Q,1=K,2=V (pair never straddles)
                    const int d = cc & 63;
                    const size_t idx = ((size_t)(b * NH + h) * SEQ + s) * HD + d;
                    if (w == 0)      { g_Q[idx] = v0 * 0.125f; g_Q[idx + 1] = v1 * 0.125f; }
                    else if (w == 1) { g_K[idx] = v0;          g_K[idx + 1] = v1; }
                    else             { g_V[idx] = v0;          g_V[idx + 1] = v1; }
                } else {
                    Cout[(size_t)m * 1024 + gn]     = v0;
                    Cout[(size_t)m * 1024 + gn + 1] = v1;
                }
            }
        }
    }
}

// ---------------------------------------------------------------------------
// bf16x3 tensor-core flash attention (unchanged from R12 passing version).
// ---------------------------------------------------------------------------
#define ARS 72
#define PLANE_E (64*ARS)          // 4608 bf16 = 9216 B
#define ATTN3_SMEM (8*PLANE_E*2 + 768*4)   // 76800 B

__global__ __launch_bounds__(256, 2) void attn_tc_kernel()
{
    extern __shared__ __nv_bfloat16 shb[];
    __nv_bfloat16* Qh = shb;
    __nv_bfloat16* Qm = Qh + PLANE_E;
    __nv_bfloat16* Kh = Qm + PLANE_E;
    __nv_bfloat16* Km = Kh + PLANE_E;
    __nv_bfloat16* Vh = Km + PLANE_E;
    __nv_bfloat16* Vm = Vh + PLANE_E;
    __nv_bfloat16* Ph = Vm + PLANE_E;
    __nv_bfloat16* Pm = Ph + PLANE_E;
    float* wmax = (float*)(Pm + PLANE_E);   // [4][64]
    float* wsum = wmax + 256;               // [4][64]
    float* mrun = wsum + 256;
    float* lrun = mrun + 64;
    float* ssc  = lrun + 64;
    float* mnew = ssc + 64;

    const int tid  = threadIdx.x;
    const int wid  = tid >> 5;
    const int lane = tid & 31;
    const int lr = lane >> 2;
    const int lc = lane & 3;
    const int n  = blockIdx.y;           // head (b*16+h)
    const int qt = blockIdx.x;
    const int warp_m = (wid & 1) * 32;
    const int warp_n = (wid >> 1) * 16;
    const int wcol   = wid >> 1;

    const float* Qg = g_Q + ((size_t)n * SEQ + qt * 64) * HD;
    const float* Kg = g_K + (size_t)n * SEQ * HD;
    const float* Vg = g_V + (size_t)n * SEQ * HD;

    // ldmatrix lane-address offsets (bf16-element units within a plane)
    const int g8 = lane >> 3, l8 = lane & 7;
    const int aoff = ((g8 & 1) * 8 + l8) * ARS + (g8 >> 1) * 8;   // A (Q,P)
    const int boff = ((g8 >> 1) * 8 + l8) * ARS + (g8 & 1) * 8;   // B (K)
    const int voff = ((g8 & 1) * 8 + l8) * ARS + (g8 >> 1) * 8;   // V (trans)

    const uint32_t bQh = smem_u32(Qh), bQm = smem_u32(Qm);
    const uint32_t bKh = smem_u32(Kh), bKm = smem_u32(Km);
    const uint32_t bVh = smem_u32(Vh), bVm = smem_u32(Vm);
    const uint32_t bPh = smem_u32(Ph), bPm = smem_u32(Pm);

    // Stage Q
    for (int i = tid; i < 64 * 16; i += 256) {
        const int r = i >> 4, c4 = (i & 15) << 2;
        uint2 h, m;
        split4(*(const float4*)(Qg + r * HD + c4), h, m);
        *(uint2*)&Qh[r * ARS + c4] = h;
        *(uint2*)&Qm[r * ARS + c4] = m;
    }
    if (tid < 64) { mrun[tid] = -CUDART_INF_F; lrun[tid] = 0.f; }

    float o[2][2][4];
    #pragma unroll
    for (int mt = 0; mt < 2; mt++)
        #pragma unroll
        for (int nt = 0; nt < 2; nt++)
            #pragma unroll
            for (int r = 0; r < 4; r++) o[mt][nt][r] = 0.f;

    for (int kt = 0; kt < 16; kt++) {
        __syncthreads();   // prev-iter readers done (also covers Q staging)
        for (int i = tid; i < 64 * 16; i += 256) {
            const int r = i >> 4, c4 = (i & 15) << 2;
            const size_t go = (size_t)(kt * 64 + r) * HD + c4;
            uint2 h, m;
            split4(*(const float4*)(Kg + go), h, m);
            *(uint2*)&Kh[r * ARS + c4] = h;
            *(uint2*)&Km[r * ARS + c4] = m;
            split4(*(const float4*)(Vg + go), h, m);
            *(uint2*)&Vh[r * ARS + c4] = h;
            *(uint2*)&Vm[r * ARS + c4] = m;
        }
        __syncthreads();

        // ---- S = Q @ K^T (bf16x3) ----
        float s[2][2][4];
        #pragma unroll
        for (int mt = 0; mt < 2; mt++)
            #pragma unroll
            for (int nt = 0; nt < 2; nt++)
                #pragma unroll
                for (int r = 0; r < 4; r++) s[mt][nt][r] = 0.f;

        #pragma unroll
        for (int ks = 0; ks < 4; ks++) {
            uint32_t kh4[4], km4[4];
            const uint32_t kOff = 2u * (warp_n * ARS + ks * 16 + boff);
            ldsm_x4(kh4, bKh + kOff);
            ldsm_x4(km4, bKm + kOff);
            #pragma unroll
            for (int mt = 0; mt < 2; mt++) {
                uint32_t qh4[4], qm4[4];
                const uint32_t qOff = 2u * ((warp_m + mt * 16) * ARS + ks * 16 + aoff);
                ldsm_x4(qh4, bQh + qOff);
                ldsm_x4(qm4, bQm + qOff);
                #pragma unroll
                for (int nt = 0; nt < 2; nt++) {
                    mma16(s[mt][nt], qh4, &kh4[nt * 2]);
                    mma16(s[mt][nt], qh4, &km4[nt * 2]);
                    mma16(s[mt][nt], qm4, &kh4[nt * 2]);
                }
            }
        }

        // ---- row max partials ----
        #pragma unroll
        for (int mt = 0; mt < 2; mt++) {
            float m0 = fmaxf(fmaxf(s[mt][0][0], s[mt][0][1]), fmaxf(s[mt][1][0], s[mt][1][1]));
            float m1 = fmaxf(fmaxf(s[mt][0][2], s[mt][0][3]), fmaxf(s[mt][1][2], s[mt][1][3]));
            m0 = fmaxf(m0, __shfl_xor_sync(0xffffffffu, m0, 1));
            m0 = fmaxf(m0, __shfl_xor_sync(0xffffffffu, m0, 2));
            m1 = fmaxf(m1, __shfl_xor_sync(0xffffffffu, m1, 1));
            m1 = fmaxf(m1, __shfl_xor_sync(0xffffffffu, m1, 2));
            if (lc == 0) {
                wmax[wcol * 64 + warp_m + mt * 16 + lr]     = m0;
                wmax[wcol * 64 + warp_m + mt * 16 + lr + 8] = m1;
            }
        }
        __syncthreads();
        if (tid < 64) {
            const float mo = mrun[tid];
            float mn = fmaxf(fmaxf(wmax[tid], wmax[64 + tid]),
                             fmaxf(wmax[128 + tid], wmax[192 + tid]));
            mn = fmaxf(mn, mo);
            mnew[tid] = mn;
            ssc[tid]  = __expf(mo - mn);
            mrun[tid] = mn;
        }
        __syncthreads();

        // ---- P = exp(S - mnew) -> bf16 hi/mid planes, sums, rescale O ----
        #pragma unroll
        for (int mt = 0; mt < 2; mt++) {
            const int r0 = warp_m + mt * 16 + lr;
            const float mn0 = mnew[r0], mn1 = mnew[r0 + 8];
            float ps0 = 0.f, ps1 = 0.f;
            #pragma unroll
            for (int nt = 0; nt < 2; nt++) {
                const float p0 = __expf(s[mt][nt][0] - mn0);
                const float p1 = __expf(s[mt][nt][1] - mn0);
                const float p2 = __expf(s[mt][nt][2] - mn1);
                const float p3 = __expf(s[mt][nt][3] - mn1);
                ps0 += p0 + p1; ps1 += p2 + p3;
                uint16_t hb0, hb1, hb2, hb3;
                const float hv0 = bf16_val(p0, hb0);
                const float hv1 = bf16_val(p1, hb1);
                const float hv2 = bf16_val(p2, hb2);
                const float hv3 = bf16_val(p3, hb3);
                const int cbase = warp_n + nt * 8 + 2 * lc;
                *(uint32_t*)&Ph[r0 * ARS + cbase] =
                    (uint32_t)hb0 | ((uint32_t)hb1 << 16);
                *(uint32_t*)&Pm[r0 * ARS + cbase] =
                    (uint32_t)bf16_bits(p0 - hv0) | ((uint32_t)bf16_bits(p1 - hv1) << 16);
                *(uint32_t*)&Ph[(r0 + 8) * ARS + cbase] =
                    (uint32_t)hb2 | ((uint32_t)hb3 << 16);
                *(uint32_t*)&Pm[(r0 + 8) * ARS + cbase] =
                    (uint32_t)bf16_bits(p2 - hv2) | ((uint32_t)bf16_bits(p3 - hv3) << 16);
            }
            ps0 += __shfl_xor_sync(0xffffffffu, ps0, 1);
            ps0 += __shfl_xor_sync(0xffffffffu, ps0, 2);
            ps1 += __shfl_xor_sync(0xffffffffu, ps1, 1);
            ps1 += __shfl_xor_sync(0xffffffffu, ps1, 2);
            if (lc == 0) {
                wsum[wcol * 64 + r0]     = ps0;
                wsum[wcol * 64 + r0 + 8] = ps1;
            }
            const float sc0 = ssc[r0], sc1 = ssc[r0 + 8];
            #pragma unroll
            for (int nt = 0; nt < 2; nt++) {
                o[mt][nt][0] *= sc0; o[mt][nt][1] *= sc0;
                o[mt][nt][2] *= sc1; o[mt][nt][3] *= sc1;
            }
        }
        __syncthreads();
        if (tid < 64)
            lrun[tid] = lrun[tid] * ssc[tid]
                      + (wsum[tid] + wsum[64 + tid] + wsum[128 + tid] + wsum[192 + tid]);

        // ---- O += P @ V (bf16x3; V B-operand via ldmatrix.trans) ----
        #pragma unroll
        for (int ks = 0; ks < 4; ks++) {
            uint32_t vh4[4], vm4[4];
            const uint32_t vOff = 2u * (ks * 16 * ARS + warp_n + voff);
            ldsm_x4_t(vh4, bVh + vOff);
            ldsm_x4_t(vm4, bVm + vOff);
            #pragma unroll
            for (int mt = 0; mt < 2; mt++) {
                uint32_t ph4[4], pm4[4];
                const uint32_t pOff = 2u * ((warp_m + mt * 16) * ARS + ks * 16 + aoff);
                ldsm_x4(ph4, bPh + pOff);
                ldsm_x4(pm4, bPm + pOff);
                #pragma unroll
                for (int nt = 0; nt < 2; nt++) {
                    mma16(o[mt][nt], ph4, &vh4[nt * 2]);
                    mma16(o[mt][nt], ph4, &vm4[nt * 2]);
                    mma16(o[mt][nt], pm4, &vh4[nt * 2]);
                }
            }
        }
    }

    __syncthreads();
    // Normalize and store ctx bf16 hi/mid splits to [s,b,e]
    const int b = n >> 4;
    const int h = n & 15;
    #pragma unroll
    for (int mt = 0; mt < 2; mt++) {
        const int r0 = warp_m + mt * 16 + lr;
        const float li0 = 1.0f / lrun[r0];
        const float li1 = 1.0f / lrun[r0 + 8];
        #pragma unroll
        for (int nt = 0; nt < 2; nt++) {
            const int d = warp_n + nt * 8 + 2 * lc;
            #pragma unroll
            for (int half = 0; half < 2; half++) {
                const int row = r0 + half * 8;
                const float li = half ? li1 : li0;
                const float v0 = o[mt][nt][half * 2 + 0] * li;
                const float v1 = o[mt][nt][half * 2 + 1] * li;
                const size_t addr = ((size_t)(qt * 64 + row) * BATCH + b) * EMB + h * HD + d;
                uint16_t h0, h1;
                const float hv0 = bf16_val(v0, h0);
                const float hv1 = bf16_val(v1, h1);
                *(uint32_t*)&g_Ch[addr] = (uint32_t)h0 | ((uint32_t)h1 << 16);
                *(uint32_t*)&g_Cm[addr] =
                    (uint32_t)bf16_bits(v0 - hv0) | ((uint32_t)bf16_bits(v1 - hv1) << 16);
            }
        }
    }
}

// ---------------------------------------------------------------------------
extern "C" void kernel_launch(void* const* d_in, const int* in_sizes, int n_in,
                              void* d_out, int out_size)
{
    const float* X  = (const float*)d_in[0];  // query [S,B,E]
    const float* Wq = (const float*)d_in[3];  // in_proj_w [3E,E]
    const float* bq = (const float*)d_in[4];  // in_proj_b [3E]
    const float* Wo = (const float*)d_in[5];  // out_proj_w [E,E]
    const float* bo = (const float*)d_in[6];  // out_proj_b [E]
    float* out = (float*)d_out;

    cudaFuncSetAttribute(attn_tc_kernel,
                         cudaFuncAttributeMaxDynamicSharedMemorySize, ATTN3_SMEM);
    cudaFuncSetAttribute(tc_gemm<0>,
                         cudaFuncAttributeMaxDynamicSharedMemorySize, G_SMEM);
    cudaFuncSetAttribute(tc_gemm<1>,
                         cudaFuncAttributeMaxDynamicSharedMemorySize, G_SMEM);

    __nv_bfloat16 *xh, *xm, *wqh, *wqm, *woh, *wom, *ch, *cm;
    cudaGetSymbolAddress((void**)&xh,  g_Xh);
    cudaGetSymbolAddress((void**)&xm,  g_Xm);
    cudaGetSymbolAddress((void**)&wqh, g_Wqh);
    cudaGetSymbolAddress((void**)&wqm, g_Wqm);
    cudaGetSymbolAddress((void**)&woh, g_Woh);
    cudaGetSymbolAddress((void**)&wom, g_Wom);
    cudaGetSymbolAddress((void**)&ch,  g_Ch);
    cudaGetSymbolAddress((void**)&cm,  g_Cm);

    // 0) bf16 hi/mid splits of inputs and weights
    split_bf16_kernel<<<(MROWS*EMB/4 + 255)/256, 256>>>(
        (const float4*)X, (uint2*)xh, (uint2*)xm, MROWS*EMB/4);
    split_bf16_kernel<<<(3*EMB*EMB/4 + 255)/256, 256>>>(
        (const float4*)Wq, (uint2*)wqh, (uint2*)wqm, 3*EMB*EMB/4);
    split_bf16_kernel<<<(EMB*EMB/4 + 255)/256, 256>>>(
        (const float4*)Wo, (uint2*)woh, (uint2*)wom, EMB*EMB/4);

    // 1) QKV projection (mma.sync bf16x3, 3-stage pipeline) + scatter
    tc_gemm<0><<<dim3(3072/128, MROWS/128), 256, G_SMEM>>>(xh, xm, wqh, wqm, bq, nullptr);

    // 2) bf16x3 tensor-core flash attention — writes ctx bf16 hi/mid splits
    attn_tc_kernel<<<dim3(SEQ/64, NHEADS_TOT), 256, ATTN3_SMEM>>>();

    // 3) Output projection (mma.sync bf16x3, 3-stage pipeline)
    tc_gemm<1><<<dim3(1024/128, MROWS/128), 256, G_SMEM>>>(ch, cm, woh, wom, bo, out);
}

// round 14
// speedup vs baseline: 1.1109x; 1.1109x over previous
#include <cuda_runtime.h>
#include <cuda_bf16.h>
#include <math_constants.h>
#include <cstdint>

// Problem constants
#define SEQ   1024
#define BATCH 8
#define EMB   1024
#define NH    16
#define HD    64
#define MROWS (SEQ*BATCH)        // 8192
#define NHEADS_TOT (BATCH*NH)    // 128

// ---------------------------------------------------------------------------
// Scratch (device globals; allocation-free)
// ---------------------------------------------------------------------------
__device__ float g_Q[NHEADS_TOT * SEQ * HD];   // [n][s][d], pre-scaled by 1/8
__device__ float g_K[NHEADS_TOT * SEQ * HD];
__device__ float g_V[NHEADS_TOT * SEQ * HD];
__device__ __nv_bfloat16 g_Xh[MROWS * EMB];
__device__ __nv_bfloat16 g_Xm[MROWS * EMB];
__device__ __nv_bfloat16 g_Wqh[3 * EMB * EMB];
__device__ __nv_bfloat16 g_Wqm[3 * EMB * EMB];
__device__ __nv_bfloat16 g_Woh[EMB * EMB];
__device__ __nv_bfloat16 g_Wom[EMB * EMB];
__device__ __nv_bfloat16 g_Ch[MROWS * EMB];    // ctx hi split, [s,b,e]
__device__ __nv_bfloat16 g_Cm[MROWS * EMB];    // ctx mid split

// ---------------------------------------------------------------------------
// Helpers (sm_103 plain: mma.sync + cp.async + ldmatrix only)
// ---------------------------------------------------------------------------
__device__ __forceinline__ uint32_t smem_u32(const void* p) {
    uint32_t a;
    asm("{ .reg .u64 t; cvta.to.shared.u64 t, %1; cvt.u32.u64 %0, t; }"
        : "=r"(a) : "l"(p));
    return a;
}

__device__ __forceinline__ void cp16(uint32_t dst, const void* src) {
    asm volatile("cp.async.cg.shared.global [%0], [%1], 16;" :: "r"(dst), "l"(src));
}

__device__ __forceinline__ uint16_t bf16_bits(float x) {
    return __bfloat16_as_ushort(__float2bfloat16(x));
}
__device__ __forceinline__ float bf16_val(float x, uint16_t& bits) {
    __nv_bfloat16 h = __float2bfloat16(x);
    bits = __bfloat16_as_ushort(h);
    return __bfloat162float(h);
}

// bf16 MMA: D += A(16x16) * B(16x8)^T
__device__ __forceinline__ void mma16(float* c, const uint32_t* a, const uint32_t* b) {
    asm volatile(
        "mma.sync.aligned.m16n8k16.row.col.f32.bf16.bf16.f32 "
        "{%0,%1,%2,%3}, {%4,%5,%6,%7}, {%8,%9}, {%0,%1,%2,%3};"
        : "+f"(c[0]), "+f"(c[1]), "+f"(c[2]), "+f"(c[3])
        : "r"(a[0]), "r"(a[1]), "r"(a[2]), "r"(a[3]), "r"(b[0]), "r"(b[1]));
}

__device__ __forceinline__ void ldsm_x4(uint32_t* r, uint32_t addr) {
    asm volatile("ldmatrix.sync.aligned.m8n8.x4.shared.b16 {%0,%1,%2,%3}, [%4];"
        : "=r"(r[0]), "=r"(r[1]), "=r"(r[2]), "=r"(r[3]) : "r"(addr));
}
__device__ __forceinline__ void ldsm_x4_t(uint32_t* r, uint32_t addr) {
    asm volatile("ldmatrix.sync.aligned.m8n8.x4.trans.shared.b16 {%0,%1,%2,%3}, [%4];"
        : "=r"(r[0]), "=r"(r[1]), "=r"(r[2]), "=r"(r[3]) : "r"(addr));
}

// float4 -> packed bf16 hi / mid uint2
__device__ __forceinline__ void split4(float4 v, uint2& h, uint2& m) {
    uint16_t hb0, hb1, hb2, hb3;
    float h0 = bf16_val(v.x, hb0);
    float h1 = bf16_val(v.y, hb1);
    float h2 = bf16_val(v.z, hb2);
    float h3 = bf16_val(v.w, hb3);
    uint16_t m0 = bf16_bits(v.x - h0), m1 = bf16_bits(v.y - h1);
    uint16_t m2 = bf16_bits(v.z - h2), m3 = bf16_bits(v.w - h3);
    h = make_uint2((uint32_t)hb0 | ((uint32_t)hb1 << 16),
                   (uint32_t)hb2 | ((uint32_t)hb3 << 16));
    m = make_uint2((uint32_t)m0 | ((uint32_t)m1 << 16),
                   (uint32_t)m2 | ((uint32_t)m3 << 16));
}

// ---------------------------------------------------------------------------
// Split kernel: x -> (hi = bf16(x), mid = bf16(x - hi)), packed 2x bf16/u32
// ---------------------------------------------------------------------------
__global__ __launch_bounds__(256) void split_bf16_kernel(
    const float4* __restrict__ src, uint2* __restrict__ hi,
    uint2* __restrict__ mid, int n4)
{
    int i = blockIdx.x * 256 + threadIdx.x;
    if (i >= n4) return;
    uint2 h, m;
    split4(src[i], h, m);
    hi[i] = h; mid[i] = m;
}

// ---------------------------------------------------------------------------
// bf16x3 GEMM via mma.sync: C = A @ B^T + bias.
// Block 128x128, BK=32, 2-stage cp.async, 256 threads, 2 CTAs/SM.
// 8 warps in 2(m)x4(n); warp tile 64x32 = 4x4 m16n8k16 tiles.
// Fragments via ldmatrix.x4 (A m16k16 tiles; B n16k16 blocks -> 2 n8 tiles).
// ---------------------------------------------------------------------------
#define BKE   32
#define RS    40
#define TILE_E (128*RS)
#define TILE_B (TILE_E*2)
#define STAGE_E (4*TILE_E)
#define STAGE_B (4*TILE_B)        // 40960 bytes
#define G_SMEM (2*STAGE_B)        // 81920 bytes -> 2 CTAs/SM
#define NCHUNK (1024/BKE)

template<int MODE>
__global__ __launch_bounds__(256, 2)
void tc_gemm(const __nv_bfloat16* __restrict__ Ah, const __nv_bfloat16* __restrict__ Am,
             const __nv_bfloat16* __restrict__ Bh, const __nv_bfloat16* __restrict__ Bm,
             const float* __restrict__ bias, float* __restrict__ Cout)
{
    extern __shared__ __nv_bfloat16 smbf[];
    const int tid  = threadIdx.x;
    const int wid  = tid >> 5;
    const int lane = tid & 31;
    const int m0 = blockIdx.y * 128;
    const int n0 = blockIdx.x * 128;
    const int warp_m = (wid & 1) * 64;
    const int warp_n = (wid >> 1) * 32;
    const int lr = lane >> 2;
    const int lc = lane & 3;

    // ldmatrix lane-address offsets (bf16-element units)
    const int g8 = lane >> 3, l8 = lane & 7;
    const int aoff = ((g8 & 1) * 8 + l8) * RS + (g8 >> 1) * 8;   // A m16k16
    const int boff = ((g8 >> 1) * 8 + l8) * RS + (g8 & 1) * 8;   // B n16k16

    float acc[4][4][4];
    #pragma unroll
    for (int mt = 0; mt < 4; mt++)
        #pragma unroll
        for (int nt = 0; nt < 4; nt++)
            #pragma unroll
            for (int r = 0; r < 4; r++) acc[mt][nt][r] = 0.0f;

    const uint32_t smb = smem_u32(smbf);

    auto load_chunk = [&](int st, int k0) {
        const uint32_t sb = smb + (uint32_t)st * STAGE_B;
        #pragma unroll
        for (int i = 0; i < 2; i++) {
            const int idx = tid + i * 256;
            const int r = idx >> 2, q = idx & 3;
            const uint32_t o = (uint32_t)r * (RS * 2) + (uint32_t)q * 16;
            const size_t ga = (size_t)(m0 + r) * 1024 + k0 + q * 8;
            const size_t gb = (size_t)(n0 + r) * 1024 + k0 + q * 8;
            cp16(sb + 0 * TILE_B + o, Ah + ga);
            cp16(sb + 1 * TILE_B + o, Am + ga);
            cp16(sb + 2 * TILE_B + o, Bh + gb);
            cp16(sb + 3 * TILE_B + o, Bm + gb);
        }
        asm volatile("cp.async.commit_group;" ::: "memory");
    };

    load_chunk(0, 0);
    load_chunk(1, BKE);

    for (int c = 0; c < NCHUNK; c++) {
        if (c < NCHUNK - 1) asm volatile("cp.async.wait_group 1;" ::: "memory");
        else                asm volatile("cp.async.wait_group 0;" ::: "memory");
        __syncthreads();

        const uint32_t sA_h = smb + (uint32_t)(c & 1) * STAGE_B;
        const uint32_t sA_m = sA_h + TILE_B;
        const uint32_t sB_h = sA_h + 2 * TILE_B;
        const uint32_t sB_m = sA_h + 3 * TILE_B;

        #pragma unroll
        for (int ks = 0; ks < 2; ks++) {
            const int k0 = ks * 16;
            uint32_t bh[2][4], bm[2][4];
            #pragma unroll
            for (int nb = 0; nb < 2; nb++) {
                const uint32_t off = 2u * ((uint32_t)(warp_n + nb * 16) * RS + k0 + boff);
                ldsm_x4(bh[nb], sB_h + off);
                ldsm_x4(bm[nb], sB_m + off);
            }
            #pragma unroll
            for (int mt = 0; mt < 4; mt++) {
                uint32_t ah4[4], am4[4];
                const uint32_t off = 2u * ((uint32_t)(warp_m + mt * 16) * RS + k0 + aoff);
                ldsm_x4(ah4, sA_h + off);
                ldsm_x4(am4, sA_m + off);
                #pragma unroll
                for (int nt = 0; nt < 4; nt++) {
                    const uint32_t* bbh = &bh[nt >> 1][(nt & 1) * 2];
                    const uint32_t* bbm = &bm[nt >> 1][(nt & 1) * 2];
                    mma16(acc[mt][nt], ah4, bbh);
                    mma16(acc[mt][nt], ah4, bbm);
                    mma16(acc[mt][nt], am4, bbh);
                }
            }
        }
        __syncthreads();
        if (c + 2 < NCHUNK) load_chunk(c & 1, (c + 2) * BKE);
    }

    // ---- Epilogue: direct global stores (pairs of consecutive n) ----
    #pragma unroll
    for (int mt = 0; mt < 4; mt++) {
        #pragma unroll
        for (int nt = 0; nt < 4; nt++) {
            const int gm = m0 + warp_m + mt * 16 + lr;
            const int gn = n0 + warp_n + nt * 8 + lc * 2;
            #pragma unroll
            for (int half = 0; half < 2; half++) {
                const int m = gm + half * 8;
                const float v0 = acc[mt][nt][half * 2 + 0] + __ldg(&bias[gn]);
                const float v1 = acc[mt][nt][half * 2 + 1] + __ldg(&bias[gn + 1]);
                if (MODE == 0) {
                    const int s = m >> 3;
                    const int b = m & 7;
                    const int h = gn / 192;
                    const int cc = gn - h * 192;
                    const int w = cc >> 6;           // 0=Q,1=K,2=V (pair never straddles)
                    const int d = cc & 63;
                    const size_t idx = ((size_t)(b * NH + h) * SEQ + s) * HD + d;
                    if (w == 0)      { g_Q[idx] = v0 * 0.125f; g_Q[idx + 1] = v1 * 0.125f; }
                    else if (w == 1) { g_K[idx] = v0;          g_K[idx + 1] = v1; }
                    else             { g_V[idx] = v0;          g_V[idx + 1] = v1; }
                } else {
                    Cout[(size_t)m * 1024 + gn]     = v0;
                    Cout[(size_t)m * 1024 + gn + 1] = v1;
                }
            }
        }
    }
}

// ---------------------------------------------------------------------------
// bf16x3 tensor-core flash attention (unchanged from R12 passing version).
// ---------------------------------------------------------------------------
#define ARS 72
#define PLANE_E (64*ARS)          // 4608 bf16 = 9216 B
#define ATTN3_SMEM (8*PLANE_E*2 + 768*4)   // 76800 B

__global__ __launch_bounds__(256, 2) void attn_tc_kernel()
{
    extern __shared__ __nv_bfloat16 shb[];
    __nv_bfloat16* Qh = shb;
    __nv_bfloat16* Qm = Qh + PLANE_E;
    __nv_bfloat16* Kh = Qm + PLANE_E;
    __nv_bfloat16* Km = Kh + PLANE_E;
    __nv_bfloat16* Vh = Km + PLANE_E;
    __nv_bfloat16* Vm = Vh + PLANE_E;
    __nv_bfloat16* Ph = Vm + PLANE_E;
    __nv_bfloat16* Pm = Ph + PLANE_E;
    float* wmax = (float*)(Pm + PLANE_E);   // [4][64]
    float* wsum = wmax + 256;               // [4][64]
    float* mrun = wsum + 256;
    float* lrun = mrun + 64;
    float* ssc  = lrun + 64;
    float* mnew = ssc + 64;

    const int tid  = threadIdx.x;
    const int wid  = tid >> 5;
    const int lane = tid & 31;
    const int lr = lane >> 2;
    const int lc = lane & 3;
    const int n  = blockIdx.y;           // head (b*16+h)
    const int qt = blockIdx.x;
    const int warp_m = (wid & 1) * 32;
    const int warp_n = (wid >> 1) * 16;
    const int wcol   = wid >> 1;

    const float* Qg = g_Q + ((size_t)n * SEQ + qt * 64) * HD;
    const float* Kg = g_K + (size_t)n * SEQ * HD;
    const float* Vg = g_V + (size_t)n * SEQ * HD;

    // ldmatrix lane-address offsets (bf16-element units within a plane)
    const int g8 = lane >> 3, l8 = lane & 7;
    const int aoff = ((g8 & 1) * 8 + l8) * ARS + (g8 >> 1) * 8;   // A (Q,P)
    const int boff = ((g8 >> 1) * 8 + l8) * ARS + (g8 & 1) * 8;   // B (K)
    const int voff = ((g8 & 1) * 8 + l8) * ARS + (g8 >> 1) * 8;   // V (trans)

    const uint32_t bQh = smem_u32(Qh), bQm = smem_u32(Qm);
    const uint32_t bKh = smem_u32(Kh), bKm = smem_u32(Km);
    const uint32_t bVh = smem_u32(Vh), bVm = smem_u32(Vm);
    const uint32_t bPh = smem_u32(Ph), bPm = smem_u32(Pm);

    // Stage Q
    for (int i = tid; i < 64 * 16; i += 256) {
        const int r = i >> 4, c4 = (i & 15) << 2;
        uint2 h, m;
        split4(*(const float4*)(Qg + r * HD + c4), h, m);
        *(uint2*)&Qh[r * ARS + c4] = h;
        *(uint2*)&Qm[r * ARS + c4] = m;
    }
    if (tid < 64) { mrun[tid] = -CUDART_INF_F; lrun[tid] = 0.f; }

    float o[2][2][4];
    #pragma unroll
    for (int mt = 0; mt < 2; mt++)
        #pragma unroll
        for (int nt = 0; nt < 2; nt++)
            #pragma unroll
            for (int r = 0; r < 4; r++) o[mt][nt][r] = 0.f;

    for (int kt = 0; kt < 16; kt++) {
        __syncthreads();   // prev-iter readers done (also covers Q staging)
        for (int i = tid; i < 64 * 16; i += 256) {
            const int r = i >> 4, c4 = (i & 15) << 2;
            const size_t go = (size_t)(kt * 64 + r) * HD + c4;
            uint2 h, m;
            split4(*(const float4*)(Kg + go), h, m);
            *(uint2*)&Kh[r * ARS + c4] = h;
            *(uint2*)&Km[r * ARS + c4] = m;
            split4(*(const float4*)(Vg + go), h, m);
            *(uint2*)&Vh[r * ARS + c4] = h;
            *(uint2*)&Vm[r * ARS + c4] = m;
        }
        __syncthreads();

        // ---- S = Q @ K^T (bf16x3) ----
        float s[2][2][4];
        #pragma unroll
        for (int mt = 0; mt < 2; mt++)
            #pragma unroll
            for (int nt = 0; nt < 2; nt++)
                #pragma unroll
                for (int r = 0; r < 4; r++) s[mt][nt][r] = 0.f;

        #pragma unroll
        for (int ks = 0; ks < 4; ks++) {
            uint32_t kh4[4], km4[4];
            const uint32_t kOff = 2u * (warp_n * ARS + ks * 16 + boff);
            ldsm_x4(kh4, bKh + kOff);
            ldsm_x4(km4, bKm + kOff);
            #pragma unroll
            for (int mt = 0; mt < 2; mt++) {
                uint32_t qh4[4], qm4[4];
                const uint32_t qOff = 2u * ((warp_m + mt * 16) * ARS + ks * 16 + aoff);
                ldsm_x4(qh4, bQh + qOff);
                ldsm_x4(qm4, bQm + qOff);
                #pragma unroll
                for (int nt = 0; nt < 2; nt++) {
                    mma16(s[mt][nt], qh4, &kh4[nt * 2]);
                    mma16(s[mt][nt], qh4, &km4[nt * 2]);
                    mma16(s[mt][nt], qm4, &kh4[nt * 2]);
                }
            }
        }

        // ---- row max partials ----
        #pragma unroll
        for (int mt = 0; mt < 2; mt++) {
            float m0 = fmaxf(fmaxf(s[mt][0][0], s[mt][0][1]), fmaxf(s[mt][1][0], s[mt][1][1]));
            float m1 = fmaxf(fmaxf(s[mt][0][2], s[mt][0][3]), fmaxf(s[mt][1][2], s[mt][1][3]));
            m0 = fmaxf(m0, __shfl_xor_sync(0xffffffffu, m0, 1));
            m0 = fmaxf(m0, __shfl_xor_sync(0xffffffffu, m0, 2));
            m1 = fmaxf(m1, __shfl_xor_sync(0xffffffffu, m1, 1));
            m1 = fmaxf(m1, __shfl_xor_sync(0xffffffffu, m1, 2));
            if (lc == 0) {
                wmax[wcol * 64 + warp_m + mt * 16 + lr]     = m0;
                wmax[wcol * 64 + warp_m + mt * 16 + lr + 8] = m1;
            }
        }
        __syncthreads();
        if (tid < 64) {
            const float mo = mrun[tid];
            float mn = fmaxf(fmaxf(wmax[tid], wmax[64 + tid]),
                             fmaxf(wmax[128 + tid], wmax[192 + tid]));
            mn = fmaxf(mn, mo);
            mnew[tid] = mn;
            ssc[tid]  = __expf(mo - mn);
            mrun[tid] = mn;
        }
        __syncthreads();

        // ---- P = exp(S - mnew) -> bf16 hi/mid planes, sums, rescale O ----
        #pragma unroll
        for (int mt = 0; mt < 2; mt++) {
            const int r0 = warp_m + mt * 16 + lr;
            const float mn0 = mnew[r0], mn1 = mnew[r0 + 8];
            float ps0 = 0.f, ps1 = 0.f;
            #pragma unroll
            for (int nt = 0; nt < 2; nt++) {
                const float p0 = __expf(s[mt][nt][0] - mn0);
                const float p1 = __expf(s[mt][nt][1] - mn0);
                const float p2 = __expf(s[mt][nt][2] - mn1);
                const float p3 = __expf(s[mt][nt][3] - mn1);
                ps0 += p0 + p1; ps1 += p2 + p3;
                uint16_t hb0, hb1, hb2, hb3;
                const float hv0 = bf16_val(p0, hb0);
                const float hv1 = bf16_val(p1, hb1);
                const float hv2 = bf16_val(p2, hb2);
                const float hv3 = bf16_val(p3, hb3);
                const int cbase = warp_n + nt * 8 + 2 * lc;
                *(uint32_t*)&Ph[r0 * ARS + cbase] =
                    (uint32_t)hb0 | ((uint32_t)hb1 << 16);
                *(uint32_t*)&Pm[r0 * ARS + cbase] =
                    (uint32_t)bf16_bits(p0 - hv0) | ((uint32_t)bf16_bits(p1 - hv1) << 16);
                *(uint32_t*)&Ph[(r0 + 8) * ARS + cbase] =
                    (uint32_t)hb2 | ((uint32_t)hb3 << 16);
                *(uint32_t*)&Pm[(r0 + 8) * ARS + cbase] =
                    (uint32_t)bf16_bits(p2 - hv2) | ((uint32_t)bf16_bits(p3 - hv3) << 16);
            }
            ps0 += __shfl_xor_sync(0xffffffffu, ps0, 1);
            ps0 += __shfl_xor_sync(0xffffffffu, ps0, 2);
            ps1 += __shfl_xor_sync(0xffffffffu, ps1, 1);
            ps1 += __shfl_xor_sync(0xffffffffu, ps1, 2);
            if (lc == 0) {
                wsum[wcol * 64 + r0]     = ps0;
                wsum[wcol * 64 + r0 + 8] = ps1;
            }
            const float sc0 = ssc[r0], sc1 = ssc[r0 + 8];
            #pragma unroll
            for (int nt = 0; nt < 2; nt++) {
                o[mt][nt][0] *= sc0; o[mt][nt][1] *= sc0;
                o[mt][nt][2] *= sc1; o[mt][nt][3] *= sc1;
            }
        }
        __syncthreads();
        if (tid < 64)
            lrun[tid] = lrun[tid] * ssc[tid]
                      + (wsum[tid] + wsum[64 + tid] + wsum[128 + tid] + wsum[192 + tid]);

        // ---- O += P @ V (bf16x3; V B-operand via ldmatrix.trans) ----
        #pragma unroll
        for (int ks = 0; ks < 4; ks++) {
            uint32_t vh4[4], vm4[4];
            const uint32_t vOff = 2u * (ks * 16 * ARS + warp_n + voff);
            ldsm_x4_t(vh4, bVh + vOff);
            ldsm_x4_t(vm4, bVm + vOff);
            #pragma unroll
            for (int mt = 0; mt < 2; mt++) {
                uint32_t ph4[4], pm4[4];
                const uint32_t pOff = 2u * ((warp_m + mt * 16) * ARS + ks * 16 + aoff);
                ldsm_x4(ph4, bPh + pOff);
                ldsm_x4(pm4, bPm + pOff);
                #pragma unroll
                for (int nt = 0; nt < 2; nt++) {
                    mma16(o[mt][nt], ph4, &vh4[nt * 2]);
                    mma16(o[mt][nt], ph4, &vm4[nt * 2]);
                    mma16(o[mt][nt], pm4, &vh4[nt * 2]);
                }
            }
        }
    }

    __syncthreads();
    // Normalize and store ctx bf16 hi/mid splits to [s,b,e]
    const int b = n >> 4;
    const int h = n & 15;
    #pragma unroll
    for (int mt = 0; mt < 2; mt++) {
        const int r0 = warp_m + mt * 16 + lr;
        const float li0 = 1.0f / lrun[r0];
        const float li1 = 1.0f / lrun[r0 + 8];
        #pragma unroll
        for (int nt = 0; nt < 2; nt++) {
            const int d = warp_n + nt * 8 + 2 * lc;
            #pragma unroll
            for (int half = 0; half < 2; half++) {
                const int row = r0 + half * 8;
                const float li = half ? li1 : li0;
                const float v0 = o[mt][nt][half * 2 + 0] * li;
                const float v1 = o[mt][nt][half * 2 + 1] * li;
                const size_t addr = ((size_t)(qt * 64 + row) * BATCH + b) * EMB + h * HD + d;
                uint16_t h0, h1;
                const float hv0 = bf16_val(v0, h0);
                const float hv1 = bf16_val(v1, h1);
                *(uint32_t*)&g_Ch[addr] = (uint32_t)h0 | ((uint32_t)h1 << 16);
                *(uint32_t*)&g_Cm[addr] =
                    (uint32_t)bf16_bits(v0 - hv0) | ((uint32_t)bf16_bits(v1 - hv1) << 16);
            }
        }
    }
}

// ---------------------------------------------------------------------------
extern "C" void kernel_launch(void* const* d_in, const int* in_sizes, int n_in,
                              void* d_out, int out_size)
{
    const float* X  = (const float*)d_in[0];  // query [S,B,E]
    const float* Wq = (const float*)d_in[3];  // in_proj_w [3E,E]
    const float* bq = (const float*)d_in[4];  // in_proj_b [3E]
    const float* Wo = (const float*)d_in[5];  // out_proj_w [E,E]
    const float* bo = (const float*)d_in[6];  // out_proj_b [E]
    float* out = (float*)d_out;

    cudaFuncSetAttribute(attn_tc_kernel,
                         cudaFuncAttributeMaxDynamicSharedMemorySize, ATTN3_SMEM);
    cudaFuncSetAttribute(tc_gemm<0>,
                         cudaFuncAttributeMaxDynamicSharedMemorySize, G_SMEM);
    cudaFuncSetAttribute(tc_gemm<1>,
                         cudaFuncAttributeMaxDynamicSharedMemorySize, G_SMEM);

    __nv_bfloat16 *xh, *xm, *wqh, *wqm, *woh, *wom, *ch, *cm;
    cudaGetSymbolAddress((void**)&xh,  g_Xh);
    cudaGetSymbolAddress((void**)&xm,  g_Xm);
    cudaGetSymbolAddress((void**)&wqh, g_Wqh);
    cudaGetSymbolAddress((void**)&wqm, g_Wqm);
    cudaGetSymbolAddress((void**)&woh, g_Woh);
    cudaGetSymbolAddress((void**)&wom, g_Wom);
    cudaGetSymbolAddress((void**)&ch,  g_Ch);
    cudaGetSymbolAddress((void**)&cm,  g_Cm);

    // 0) bf16 hi/mid splits of inputs and weights
    split_bf16_kernel<<<(MROWS*EMB/4 + 255)/256, 256>>>(
        (const float4*)X, (uint2*)xh, (uint2*)xm, MROWS*EMB/4);
    split_bf16_kernel<<<(3*EMB*EMB/4 + 255)/256, 256>>>(
        (const float4*)Wq, (uint2*)wqh, (uint2*)wqm, 3*EMB*EMB/4);
    split_bf16_kernel<<<(EMB*EMB/4 + 255)/256, 256>>>(
        (const float4*)Wo, (uint2*)woh, (uint2*)wom, EMB*EMB/4);

    // 1) QKV projection (mma.sync bf16x3, ldmatrix, 2 CTAs/SM) + scatter
    tc_gemm<0><<<dim3(3072/128, MROWS/128), 256, G_SMEM>>>(xh, xm, wqh, wqm, bq, nullptr);

    // 2) bf16x3 tensor-core flash attention — writes ctx bf16 hi/mid splits
    attn_tc_kernel<<<dim3(SEQ/64, NHEADS_TOT), 256, ATTN3_SMEM>>>();

    // 3) Output projection (mma.sync bf16x3, ldmatrix, 2 CTAs/SM)
    tc_gemm<1><<<dim3(1024/128, MROWS/128), 256, G_SMEM>>>(ch, cm, woh, wom, bo, out);
}

// round 15
// speedup vs baseline: 1.2730x; 1.1459x over previous
#include <cuda_runtime.h>
#include <cuda_bf16.h>
#include <math_constants.h>
#include <cstdint>

// Problem constants
#define SEQ   1024
#define BATCH 8
#define EMB   1024
#define NH    16
#define HD    64
#define MROWS (SEQ*BATCH)        // 8192
#define NHEADS_TOT (BATCH*NH)    // 128
#define NSH   (NHEADS_TOT*SEQ*HD)

// ---------------------------------------------------------------------------
// Scratch (device globals; allocation-free). Q/K/V stored as bf16 hi/mid
// plane pairs in [n][s][d] layout (split once in tc_gemm<0> epilogue).
// ---------------------------------------------------------------------------
__device__ __nv_bfloat16 g_Qh[NSH], g_Qm[NSH];
__device__ __nv_bfloat16 g_Kh[NSH], g_Km[NSH];
__device__ __nv_bfloat16 g_Vh[NSH], g_Vm[NSH];
__device__ __nv_bfloat16 g_Xh[MROWS * EMB];
__device__ __nv_bfloat16 g_Xm[MROWS * EMB];
__device__ __nv_bfloat16 g_Wqh[3 * EMB * EMB];
__device__ __nv_bfloat16 g_Wqm[3 * EMB * EMB];
__device__ __nv_bfloat16 g_Woh[EMB * EMB];
__device__ __nv_bfloat16 g_Wom[EMB * EMB];
__device__ __nv_bfloat16 g_Ch[MROWS * EMB];    // ctx hi split, [s,b,e]
__device__ __nv_bfloat16 g_Cm[MROWS * EMB];    // ctx mid split

// ---------------------------------------------------------------------------
// Helpers (sm_103 plain: mma.sync + cp.async + ldmatrix only)
// ---------------------------------------------------------------------------
__device__ __forceinline__ uint32_t smem_u32(const void* p) {
    uint32_t a;
    asm("{ .reg .u64 t; cvta.to.shared.u64 t, %1; cvt.u32.u64 %0, t; }"
        : "=r"(a) : "l"(p));
    return a;
}

__device__ __forceinline__ void cp16(uint32_t dst, const void* src) {
    asm volatile("cp.async.cg.shared.global [%0], [%1], 16;" :: "r"(dst), "l"(src));
}

__device__ __forceinline__ uint16_t bf16_bits(float x) {
    return __bfloat16_as_ushort(__float2bfloat16(x));
}
__device__ __forceinline__ float bf16_val(float x, uint16_t& bits) {
    __nv_bfloat16 h = __float2bfloat16(x);
    bits = __bfloat16_as_ushort(h);
    return __bfloat162float(h);
}

// bf16 MMA: D += A(16x16) * B(16x8)^T
__device__ __forceinline__ void mma16(float* c, const uint32_t* a, const uint32_t* b) {
    asm volatile(
        "mma.sync.aligned.m16n8k16.row.col.f32.bf16.bf16.f32 "
        "{%0,%1,%2,%3}, {%4,%5,%6,%7}, {%8,%9}, {%0,%1,%2,%3};"
        : "+f"(c[0]), "+f"(c[1]), "+f"(c[2]), "+f"(c[3])
        : "r"(a[0]), "r"(a[1]), "r"(a[2]), "r"(a[3]), "r"(b[0]), "r"(b[1]));
}

__device__ __forceinline__ void ldsm_x4(uint32_t* r, uint32_t addr) {
    asm volatile("ldmatrix.sync.aligned.m8n8.x4.shared.b16 {%0,%1,%2,%3}, [%4];"
        : "=r"(r[0]), "=r"(r[1]), "=r"(r[2]), "=r"(r[3]) : "r"(addr));
}
__device__ __forceinline__ void ldsm_x4_t(uint32_t* r, uint32_t addr) {
    asm volatile("ldmatrix.sync.aligned.m8n8.x4.trans.shared.b16 {%0,%1,%2,%3}, [%4];"
        : "=r"(r[0]), "=r"(r[1]), "=r"(r[2]), "=r"(r[3]) : "r"(addr));
}

// float4 -> packed bf16 hi / mid uint2
__device__ __forceinline__ void split4(float4 v, uint2& h, uint2& m) {
    uint16_t hb0, hb1, hb2, hb3;
    float h0 = bf16_val(v.x, hb0);
    float h1 = bf16_val(v.y, hb1);
    float h2 = bf16_val(v.z, hb2);
    float h3 = bf16_val(v.w, hb3);
    uint16_t m0 = bf16_bits(v.x - h0), m1 = bf16_bits(v.y - h1);
    uint16_t m2 = bf16_bits(v.z - h2), m3 = bf16_bits(v.w - h3);
    h = make_uint2((uint32_t)hb0 | ((uint32_t)hb1 << 16),
                   (uint32_t)hb2 | ((uint32_t)hb3 << 16));
    m = make_uint2((uint32_t)m0 | ((uint32_t)m1 << 16),
                   (uint32_t)m2 | ((uint32_t)m3 << 16));
}

// ---------------------------------------------------------------------------
// Split kernel: x -> (hi = bf16(x), mid = bf16(x - hi)), packed 2x bf16/u32
// ---------------------------------------------------------------------------
__global__ __launch_bounds__(256) void split_bf16_kernel(
    const float4* __restrict__ src, uint2* __restrict__ hi,
    uint2* __restrict__ mid, int n4)
{
    int i = blockIdx.x * 256 + threadIdx.x;
    if (i >= n4) return;
    uint2 h, m;
    split4(src[i], h, m);
    hi[i] = h; mid[i] = m;
}

// ---------------------------------------------------------------------------
// bf16x3 GEMM via mma.sync: C = A @ B^T + bias.
// Block 128x128, BK=32, 2-stage cp.async, 256 threads, 2 CTAs/SM, ldmatrix.
// MODE 0: QKV proj — split result to bf16 hi/mid planes g_{Q,K,V}{h,m}.
// MODE 1: out proj — fp32 Cout + bias.
// ---------------------------------------------------------------------------
#define BKE   32
#define RS    40
#define TILE_E (128*RS)
#define TILE_B (TILE_E*2)
#define STAGE_E (4*TILE_E)
#define STAGE_B (4*TILE_B)        // 40960 bytes
#define G_SMEM (2*STAGE_B)        // 81920 bytes -> 2 CTAs/SM
#define NCHUNK (1024/BKE)

template<int MODE>
__global__ __launch_bounds__(256, 2)
void tc_gemm(const __nv_bfloat16* __restrict__ Ah, const __nv_bfloat16* __restrict__ Am,
             const __nv_bfloat16* __restrict__ Bh, const __nv_bfloat16* __restrict__ Bm,
             const float* __restrict__ bias, float* __restrict__ Cout)
{
    extern __shared__ __nv_bfloat16 smbf[];
    const int tid  = threadIdx.x;
    const int wid  = tid >> 5;
    const int lane = tid & 31;
    const int m0 = blockIdx.y * 128;
    const int n0 = blockIdx.x * 128;
    const int warp_m = (wid & 1) * 64;
    const int warp_n = (wid >> 1) * 32;
    const int lr = lane >> 2;
    const int lc = lane & 3;

    // ldmatrix lane-address offsets (bf16-element units)
    const int g8 = lane >> 3, l8 = lane & 7;
    const int aoff = ((g8 & 1) * 8 + l8) * RS + (g8 >> 1) * 8;   // A m16k16
    const int boff = ((g8 >> 1) * 8 + l8) * RS + (g8 & 1) * 8;   // B n16k16

    float acc[4][4][4];
    #pragma unroll
    for (int mt = 0; mt < 4; mt++)
        #pragma unroll
        for (int nt = 0; nt < 4; nt++)
            #pragma unroll
            for (int r = 0; r < 4; r++) acc[mt][nt][r] = 0.0f;

    const uint32_t smb = smem_u32(smbf);

    auto load_chunk = [&](int st, int k0) {
        const uint32_t sb = smb + (uint32_t)st * STAGE_B;
        #pragma unroll
        for (int i = 0; i < 2; i++) {
            const int idx = tid + i * 256;
            const int r = idx >> 2, q = idx & 3;
            const uint32_t o = (uint32_t)r * (RS * 2) + (uint32_t)q * 16;
            const size_t ga = (size_t)(m0 + r) * 1024 + k0 + q * 8;
            const size_t gb = (size_t)(n0 + r) * 1024 + k0 + q * 8;
            cp16(sb + 0 * TILE_B + o, Ah + ga);
            cp16(sb + 1 * TILE_B + o, Am + ga);
            cp16(sb + 2 * TILE_B + o, Bh + gb);
            cp16(sb + 3 * TILE_B + o, Bm + gb);
        }
        asm volatile("cp.async.commit_group;" ::: "memory");
    };

    load_chunk(0, 0);
    load_chunk(1, BKE);

    for (int c = 0; c < NCHUNK; c++) {
        if (c < NCHUNK - 1) asm volatile("cp.async.wait_group 1;" ::: "memory");
        else                asm volatile("cp.async.wait_group 0;" ::: "memory");
        __syncthreads();

        const uint32_t sA_h = smb + (uint32_t)(c & 1) * STAGE_B;
        const uint32_t sA_m = sA_h + TILE_B;
        const uint32_t sB_h = sA_h + 2 * TILE_B;
        const uint32_t sB_m = sA_h + 3 * TILE_B;

        #pragma unroll
        for (int ks = 0; ks < 2; ks++) {
            const int k0 = ks * 16;
            uint32_t bh[2][4], bm[2][4];
            #pragma unroll
            for (int nb = 0; nb < 2; nb++) {
                const uint32_t off = 2u * ((uint32_t)(warp_n + nb * 16) * RS + k0 + boff);
                ldsm_x4(bh[nb], sB_h + off);
                ldsm_x4(bm[nb], sB_m + off);
            }
            #pragma unroll
            for (int mt = 0; mt < 4; mt++) {
                uint32_t ah4[4], am4[4];
                const uint32_t off = 2u * ((uint32_t)(warp_m + mt * 16) * RS + k0 + aoff);
                ldsm_x4(ah4, sA_h + off);
                ldsm_x4(am4, sA_m + off);
                #pragma unroll
                for (int nt = 0; nt < 4; nt++) {
                    const uint32_t* bbh = &bh[nt >> 1][(nt & 1) * 2];
                    const uint32_t* bbm = &bm[nt >> 1][(nt & 1) * 2];
                    mma16(acc[mt][nt], ah4, bbh);
                    mma16(acc[mt][nt], ah4, bbm);
                    mma16(acc[mt][nt], am4, bbh);
                }
            }
        }
        __syncthreads();
        if (c + 2 < NCHUNK) load_chunk(c & 1, (c + 2) * BKE);
    }

    // ---- Epilogue ----
    #pragma unroll
    for (int mt = 0; mt < 4; mt++) {
        #pragma unroll
        for (int nt = 0; nt < 4; nt++) {
            const int gm = m0 + warp_m + mt * 16 + lr;
            const int gn = n0 + warp_n + nt * 8 + lc * 2;
            #pragma unroll
            for (int half = 0; half < 2; half++) {
                const int m = gm + half * 8;
                float v0 = acc[mt][nt][half * 2 + 0] + __ldg(&bias[gn]);
                float v1 = acc[mt][nt][half * 2 + 1] + __ldg(&bias[gn + 1]);
                if (MODE == 0) {
                    const int s = m >> 3;
                    const int b = m & 7;
                    const int h = gn / 192;
                    const int cc = gn - h * 192;
                    const int w = cc >> 6;           // 0=Q,1=K,2=V (pair never straddles)
                    const int d = cc & 63;
                    const size_t idx = ((size_t)(b * NH + h) * SEQ + s) * HD + d;
                    if (w == 0) { v0 *= 0.125f; v1 *= 0.125f; }
                    uint16_t h0, h1;
                    const float hv0 = bf16_val(v0, h0);
                    const float hv1 = bf16_val(v1, h1);
                    const uint32_t hh = (uint32_t)h0 | ((uint32_t)h1 << 16);
                    const uint32_t mm = (uint32_t)bf16_bits(v0 - hv0)
                                      | ((uint32_t)bf16_bits(v1 - hv1) << 16);
                    if (w == 0)      { *(uint32_t*)&g_Qh[idx] = hh; *(uint32_t*)&g_Qm[idx] = mm; }
                    else if (w == 1) { *(uint32_t*)&g_Kh[idx] = hh; *(uint32_t*)&g_Km[idx] = mm; }
                    else             { *(uint32_t*)&g_Vh[idx] = hh; *(uint32_t*)&g_Vm[idx] = mm; }
                } else {
                    Cout[(size_t)m * 1024 + gn]     = v0;
                    Cout[(size_t)m * 1024 + gn + 1] = v1;
                }
            }
        }
    }
}

// ---------------------------------------------------------------------------
// bf16x3 tensor-core flash attention. Staging is now pure cp.async from the
// pre-split global planes (no CVTs). MMA structure identical to R14.
// ---------------------------------------------------------------------------
#define ARS 72
#define PLANE_E (64*ARS)          // 4608 bf16 = 9216 B
#define ATTN3_SMEM (8*PLANE_E*2 + 768*4)   // 76800 B

__global__ __launch_bounds__(256, 2) void attn_tc_kernel()
{
    extern __shared__ __nv_bfloat16 shb[];
    __nv_bfloat16* Qh = shb;
    __nv_bfloat16* Qm = Qh + PLANE_E;
    __nv_bfloat16* Kh = Qm + PLANE_E;
    __nv_bfloat16* Km = Kh + PLANE_E;
    __nv_bfloat16* Vh = Km + PLANE_E;
    __nv_bfloat16* Vm = Vh + PLANE_E;
    __nv_bfloat16* Ph = Vm + PLANE_E;
    __nv_bfloat16* Pm = Ph + PLANE_E;
    float* wmax = (float*)(Pm + PLANE_E);   // [4][64]
    float* wsum = wmax + 256;               // [4][64]
    float* mrun = wsum + 256;
    float* lrun = mrun + 64;
    float* ssc  = lrun + 64;
    float* mnew = ssc + 64;

    const int tid  = threadIdx.x;
    const int wid  = tid >> 5;
    const int lane = tid & 31;
    const int lr = lane >> 2;
    const int lc = lane & 3;
    const int n  = blockIdx.y;           // head (b*16+h)
    const int qt = blockIdx.x;
    const int warp_m = (wid & 1) * 32;
    const int warp_n = (wid >> 1) * 16;
    const int wcol   = wid >> 1;

    const size_t headBase = (size_t)n * SEQ * HD;
    const size_t qBase = headBase + (size_t)qt * 64 * HD;

    // ldmatrix lane-address offsets (bf16-element units within a plane)
    const int g8 = lane >> 3, l8 = lane & 7;
    const int aoff = ((g8 & 1) * 8 + l8) * ARS + (g8 >> 1) * 8;   // A (Q,P)
    const int boff = ((g8 >> 1) * 8 + l8) * ARS + (g8 & 1) * 8;   // B (K)
    const int voff = ((g8 & 1) * 8 + l8) * ARS + (g8 >> 1) * 8;   // V (trans)

    const uint32_t bQh = smem_u32(Qh), bQm = smem_u32(Qm);
    const uint32_t bKh = smem_u32(Kh), bKm = smem_u32(Km);
    const uint32_t bVh = smem_u32(Vh), bVm = smem_u32(Vm);
    const uint32_t bPh = smem_u32(Ph), bPm = smem_u32(Pm);

    // Stage Q via cp.async (64 rows x 8 quads per plane)
    #pragma unroll
    for (int i = 0; i < 2; i++) {
        const int idx = tid + i * 256;
        const int r = idx >> 3, q = idx & 7;
        const uint32_t o = (uint32_t)r * (ARS * 2) + (uint32_t)q * 16;
        const size_t go = qBase + (size_t)r * HD + q * 8;
        cp16(bQh + o, g_Qh + go);
        cp16(bQm + o, g_Qm + go);
    }
    asm volatile("cp.async.commit_group;" ::: "memory");
    if (tid < 64) { mrun[tid] = -CUDART_INF_F; lrun[tid] = 0.f; }

    float o[2][2][4];
    #pragma unroll
    for (int mt = 0; mt < 2; mt++)
        #pragma unroll
        for (int nt = 0; nt < 2; nt++)
            #pragma unroll
            for (int r = 0; r < 4; r++) o[mt][nt][r] = 0.f;

    for (int kt = 0; kt < 16; kt++) {
        __syncthreads();   // prev-iter readers of K/V/P planes done
        // Stage K,V via cp.async (no conversions — pre-split in gemm0)
        #pragma unroll
        for (int i = 0; i < 2; i++) {
            const int idx = tid + i * 256;
            const int r = idx >> 3, q = idx & 7;
            const uint32_t o2 = (uint32_t)r * (ARS * 2) + (uint32_t)q * 16;
            const size_t go = headBase + (size_t)(kt * 64 + r) * HD + q * 8;
            cp16(bKh + o2, g_Kh + go);
            cp16(bKm + o2, g_Km + go);
            cp16(bVh + o2, g_Vh + go);
            cp16(bVm + o2, g_Vm + go);
        }
        asm volatile("cp.async.commit_group;" ::: "memory");
        asm volatile("cp.async.wait_group 0;" ::: "memory");
        __syncthreads();

        // ---- S = Q @ K^T (bf16x3) ----
        float s[2][2][4];
        #pragma unroll
        for (int mt = 0; mt < 2; mt++)
            #pragma unroll
            for (int nt = 0; nt < 2; nt++)
                #pragma unroll
                for (int r = 0; r < 4; r++) s[mt][nt][r] = 0.f;

        #pragma unroll
        for (int ks = 0; ks < 4; ks++) {
            uint32_t kh4[4], km4[4];
            const uint32_t kOff = 2u * (warp_n * ARS + ks * 16 + boff);
            ldsm_x4(kh4, bKh + kOff);
            ldsm_x4(km4, bKm + kOff);
            #pragma unroll
            for (int mt = 0; mt < 2; mt++) {
                uint32_t qh4[4], qm4[4];
                const uint32_t qOff = 2u * ((warp_m + mt * 16) * ARS + ks * 16 + aoff);
                ldsm_x4(qh4, bQh + qOff);
                ldsm_x4(qm4, bQm + qOff);
                #pragma unroll
                for (int nt = 0; nt < 2; nt++) {
                    mma16(s[mt][nt], qh4, &kh4[nt * 2]);
                    mma16(s[mt][nt], qh4, &km4[nt * 2]);
                    mma16(s[mt][nt], qm4, &kh4[nt * 2]);
                }
            }
        }

        // ---- row max partials ----
        #pragma unroll
        for (int mt = 0; mt < 2; mt++) {
            float m0 = fmaxf(fmaxf(s[mt][0][0], s[mt][0][1]), fmaxf(s[mt][1][0], s[mt][1][1]));
            float m1 = fmaxf(fmaxf(s[mt][0][2], s[mt][0][3]), fmaxf(s[mt][1][2], s[mt][1][3]));
            m0 = fmaxf(m0, __shfl_xor_sync(0xffffffffu, m0, 1));
            m0 = fmaxf(m0, __shfl_xor_sync(0xffffffffu, m0, 2));
            m1 = fmaxf(m1, __shfl_xor_sync(0xffffffffu, m1, 1));
            m1 = fmaxf(m1, __shfl_xor_sync(0xffffffffu, m1, 2));
            if (lc == 0) {
                wmax[wcol * 64 + warp_m + mt * 16 + lr]     = m0;
                wmax[wcol * 64 + warp_m + mt * 16 + lr + 8] = m1;
            }
        }
        __syncthreads();
        if (tid < 64) {
            const float mo = mrun[tid];
            float mn = fmaxf(fmaxf(wmax[tid], wmax[64 + tid]),
                             fmaxf(wmax[128 + tid], wmax[192 + tid]));
            mn = fmaxf(mn, mo);
            mnew[tid] = mn;
            ssc[tid]  = __expf(mo - mn);
            mrun[tid] = mn;
        }
        __syncthreads();

        // ---- P = exp(S - mnew) -> bf16 hi/mid planes, sums, rescale O ----
        #pragma unroll
        for (int mt = 0; mt < 2; mt++) {
            const int r0 = warp_m + mt * 16 + lr;
            const float mn0 = mnew[r0], mn1 = mnew[r0 + 8];
            float ps0 = 0.f, ps1 = 0.f;
            #pragma unroll
            for (int nt = 0; nt < 2; nt++) {
                const float p0 = __expf(s[mt][nt][0] - mn0);
                const float p1 = __expf(s[mt][nt][1] - mn0);
                const float p2 = __expf(s[mt][nt][2] - mn1);
                const float p3 = __expf(s[mt][nt][3] - mn1);
                ps0 += p0 + p1; ps1 += p2 + p3;
                uint16_t hb0, hb1, hb2, hb3;
                const float hv0 = bf16_val(p0, hb0);
                const float hv1 = bf16_val(p1, hb1);
                const float hv2 = bf16_val(p2, hb2);
                const float hv3 = bf16_val(p3, hb3);
                const int cbase = warp_n + nt * 8 + 2 * lc;
                *(uint32_t*)&Ph[r0 * ARS + cbase] =
                    (uint32_t)hb0 | ((uint32_t)hb1 << 16);
                *(uint32_t*)&Pm[r0 * ARS + cbase] =
                    (uint32_t)bf16_bits(p0 - hv0) | ((uint32_t)bf16_bits(p1 - hv1) << 16);
                *(uint32_t*)&Ph[(r0 + 8) * ARS + cbase] =
                    (uint32_t)hb2 | ((uint32_t)hb3 << 16);
                *(uint32_t*)&Pm[(r0 + 8) * ARS + cbase] =
                    (uint32_t)bf16_bits(p2 - hv2) | ((uint32_t)bf16_bits(p3 - hv3) << 16);
            }
            ps0 += __shfl_xor_sync(0xffffffffu, ps0, 1);
            ps0 += __shfl_xor_sync(0xffffffffu, ps0, 2);
            ps1 += __shfl_xor_sync(0xffffffffu, ps1, 1);
            ps1 += __shfl_xor_sync(0xffffffffu, ps1, 2);
            if (lc == 0) {
                wsum[wcol * 64 + r0]     = ps0;
                wsum[wcol * 64 + r0 + 8] = ps1;
            }
            const float sc0 = ssc[r0], sc1 = ssc[r0 + 8];
            #pragma unroll
            for (int nt = 0; nt < 2; nt++) {
                o[mt][nt][0] *= sc0; o[mt][nt][1] *= sc0;
                o[mt][nt][2] *= sc1; o[mt][nt][3] *= sc1;
            }
        }
        __syncthreads();
        if (tid < 64)
            lrun[tid] = lrun[tid] * ssc[tid]
                      + (wsum[tid] + wsum[64 + tid] + wsum[128 + tid] + wsum[192 + tid]);

        // ---- O += P @ V (bf16x3; V B-operand via ldmatrix.trans) ----
        #pragma unroll
        for (int ks = 0; ks < 4; ks++) {
            uint32_t vh4[4], vm4[4];
            const uint32_t vOff = 2u * (ks * 16 * ARS + warp_n + voff);
            ldsm_x4_t(vh4, bVh + vOff);
            ldsm_x4_t(vm4, bVm + vOff);
            #pragma unroll
            for (int mt = 0; mt < 2; mt++) {
                uint32_t ph4[4], pm4[4];
                const uint32_t pOff = 2u * ((warp_m + mt * 16) * ARS + ks * 16 + aoff);
                ldsm_x4(ph4, bPh + pOff);
                ldsm_x4(pm4, bPm + pOff);
                #pragma unroll
                for (int nt = 0; nt < 2; nt++) {
                    mma16(o[mt][nt], ph4, &vh4[nt * 2]);
                    mma16(o[mt][nt], ph4, &vm4[nt * 2]);
                    mma16(o[mt][nt], pm4, &vh4[nt * 2]);
                }
            }
        }
    }

    __syncthreads();
    // Normalize and store ctx bf16 hi/mid splits to [s,b,e]
    const int b = n >> 4;
    const int h = n & 15;
    #pragma unroll
    for (int mt = 0; mt < 2; mt++) {
        const int r0 = warp_m + mt * 16 + lr;
        const float li0 = 1.0f / lrun[r0];
        const float li1 = 1.0f / lrun[r0 + 8];
        #pragma unroll
        for (int nt = 0; nt < 2; nt++) {
            const int d = warp_n + nt * 8 + 2 * lc;
            #pragma unroll
            for (int half = 0; half < 2; half++) {
                const int row = r0 + half * 8;
                const float li = half ? li1 : li0;
                const float v0 = o[mt][nt][half * 2 + 0] * li;
                const float v1 = o[mt][nt][half * 2 + 1] * li;
                const size_t addr = ((size_t)(qt * 64 + row) * BATCH + b) * EMB + h * HD + d;
                uint16_t h0, h1;
                const float hv0 = bf16_val(v0, h0);
                const float hv1 = bf16_val(v1, h1);
                *(uint32_t*)&g_Ch[addr] = (uint32_t)h0 | ((uint32_t)h1 << 16);
                *(uint32_t*)&g_Cm[addr] =
                    (uint32_t)bf16_bits(v0 - hv0) | ((uint32_t)bf16_bits(v1 - hv1) << 16);
            }
        }
    }
}

// ---------------------------------------------------------------------------
extern "C" void kernel_launch(void* const* d_in, const int* in_sizes, int n_in,
                              void* d_out, int out_size)
{
    const float* X  = (const float*)d_in[0];  // query [S,B,E]
    const float* Wq = (const float*)d_in[3];  // in_proj_w [3E,E]
    const float* bq = (const float*)d_in[4];  // in_proj_b [3E]
    const float* Wo = (const float*)d_in[5];  // out_proj_w [E,E]
    const float* bo = (const float*)d_in[6];  // out_proj_b [E]
    float* out = (float*)d_out;

    cudaFuncSetAttribute(attn_tc_kernel,
                         cudaFuncAttributeMaxDynamicSharedMemorySize, ATTN3_SMEM);
    cudaFuncSetAttribute(tc_gemm<0>,
                         cudaFuncAttributeMaxDynamicSharedMemorySize, G_SMEM);
    cudaFuncSetAttribute(tc_gemm<1>,
                         cudaFuncAttributeMaxDynamicSharedMemorySize, G_SMEM);

    __nv_bfloat16 *xh, *xm, *wqh, *wqm, *woh, *wom, *ch, *cm;
    cudaGetSymbolAddress((void**)&xh,  g_Xh);
    cudaGetSymbolAddress((void**)&xm,  g_Xm);
    cudaGetSymbolAddress((void**)&wqh, g_Wqh);
    cudaGetSymbolAddress((void**)&wqm, g_Wqm);
    cudaGetSymbolAddress((void**)&woh, g_Woh);
    cudaGetSymbolAddress((void**)&wom, g_Wom);
    cudaGetSymbolAddress((void**)&ch,  g_Ch);
    cudaGetSymbolAddress((void**)&cm,  g_Cm);

    // 0) bf16 hi/mid splits of inputs and weights
    split_bf16_kernel<<<(MROWS*EMB/4 + 255)/256, 256>>>(
        (const float4*)X, (uint2*)xh, (uint2*)xm, MROWS*EMB/4);
    split_bf16_kernel<<<(3*EMB*EMB/4 + 255)/256, 256>>>(
        (const float4*)Wq, (uint2*)wqh, (uint2*)wqm, 3*EMB*EMB/4);
    split_bf16_kernel<<<(EMB*EMB/4 + 255)/256, 256>>>(
        (const float4*)Wo, (uint2*)woh, (uint2*)wom, EMB*EMB/4);

    // 1) QKV projection (bf16x3, ldmatrix, 2 CTAs/SM) + split-scatter to planes
    tc_gemm<0><<<dim3(3072/128, MROWS/128), 256, G_SMEM>>>(xh, xm, wqh, wqm, bq, nullptr);

    // 2) bf16x3 tensor-core flash attention (cp.async staging, no CVTs)
    attn_tc_kernel<<<dim3(SEQ/64, NHEADS_TOT), 256, ATTN3_SMEM>>>();

    // 3) Output projection (bf16x3, ldmatrix, 2 CTAs/SM)
    tc_gemm<1><<<dim3(1024/128, MROWS/128), 256, G_SMEM>>>(ch, cm, woh, wom, bo, out);
}

// round 16
// speedup vs baseline: 1.3884x; 1.0906x over previous
#include <cuda_runtime.h>
#include <cuda_bf16.h>
#include <math_constants.h>
#include <cstdint>

// Problem constants
#define SEQ   1024
#define BATCH 8
#define EMB   1024
#define NH    16
#define HD    64
#define MROWS (SEQ*BATCH)        // 8192
#define NHEADS_TOT (BATCH*NH)    // 128
#define NSH   (NHEADS_TOT*SEQ*HD)

// ---------------------------------------------------------------------------
// Scratch (device globals; allocation-free). Q/K/V stored as bf16 hi/mid
// plane pairs in [n][s][d] layout (split once in tc_gemm<0> epilogue).
// ---------------------------------------------------------------------------
__device__ __nv_bfloat16 g_Qh[NSH], g_Qm[NSH];
__device__ __nv_bfloat16 g_Kh[NSH], g_Km[NSH];
__device__ __nv_bfloat16 g_Vh[NSH], g_Vm[NSH];
__device__ __nv_bfloat16 g_Xh[MROWS * EMB];
__device__ __nv_bfloat16 g_Xm[MROWS * EMB];
__device__ __nv_bfloat16 g_Wqh[3 * EMB * EMB];
__device__ __nv_bfloat16 g_Wqm[3 * EMB * EMB];
__device__ __nv_bfloat16 g_Woh[EMB * EMB];
__device__ __nv_bfloat16 g_Wom[EMB * EMB];
__device__ __nv_bfloat16 g_Ch[MROWS * EMB];    // ctx hi split, [s,b,e]
__device__ __nv_bfloat16 g_Cm[MROWS * EMB];    // ctx mid split

// ---------------------------------------------------------------------------
// Helpers (sm_103 plain: mma.sync + cp.async + ldmatrix only)
// ---------------------------------------------------------------------------
__device__ __forceinline__ uint32_t smem_u32(const void* p) {
    uint32_t a;
    asm("{ .reg .u64 t; cvta.to.shared.u64 t, %1; cvt.u32.u64 %0, t; }"
        : "=r"(a) : "l"(p));
    return a;
}

__device__ __forceinline__ void cp16(uint32_t dst, const void* src) {
    asm volatile("cp.async.cg.shared.global [%0], [%1], 16;" :: "r"(dst), "l"(src));
}

__device__ __forceinline__ uint16_t bf16_bits(float x) {
    return __bfloat16_as_ushort(__float2bfloat16(x));
}
__device__ __forceinline__ float bf16_val(float x, uint16_t& bits) {
    __nv_bfloat16 h = __float2bfloat16(x);
    bits = __bfloat16_as_ushort(h);
    return __bfloat162float(h);
}
// pack two floats into bf16x2 (lo = a, hi = b); also return hi-split residuals
__device__ __forceinline__ uint32_t pack_bf16(float a, float b) {
    return (uint32_t)bf16_bits(a) | ((uint32_t)bf16_bits(b) << 16);
}

// bf16 MMA: D += A(16x16) * B(16x8)^T
__device__ __forceinline__ void mma16(float* c, const uint32_t* a, const uint32_t* b) {
    asm volatile(
        "mma.sync.aligned.m16n8k16.row.col.f32.bf16.bf16.f32 "
        "{%0,%1,%2,%3}, {%4,%5,%6,%7}, {%8,%9}, {%0,%1,%2,%3};"
        : "+f"(c[0]), "+f"(c[1]), "+f"(c[2]), "+f"(c[3])
        : "r"(a[0]), "r"(a[1]), "r"(a[2]), "r"(a[3]), "r"(b[0]), "r"(b[1]));
}

__device__ __forceinline__ void ldsm_x4(uint32_t* r, uint32_t addr) {
    asm volatile("ldmatrix.sync.aligned.m8n8.x4.shared.b16 {%0,%1,%2,%3}, [%4];"
        : "=r"(r[0]), "=r"(r[1]), "=r"(r[2]), "=r"(r[3]) : "r"(addr));
}
__device__ __forceinline__ void ldsm_x4_t(uint32_t* r, uint32_t addr) {
    asm volatile("ldmatrix.sync.aligned.m8n8.x4.trans.shared.b16 {%0,%1,%2,%3}, [%4];"
        : "=r"(r[0]), "=r"(r[1]), "=r"(r[2]), "=r"(r[3]) : "r"(addr));
}

// float4 -> packed bf16 hi / mid uint2
__device__ __forceinline__ void split4(float4 v, uint2& h, uint2& m) {
    uint16_t hb0, hb1, hb2, hb3;
    float h0 = bf16_val(v.x, hb0);
    float h1 = bf16_val(v.y, hb1);
    float h2 = bf16_val(v.z, hb2);
    float h3 = bf16_val(v.w, hb3);
    uint16_t m0 = bf16_bits(v.x - h0), m1 = bf16_bits(v.y - h1);
    uint16_t m2 = bf16_bits(v.z - h2), m3 = bf16_bits(v.w - h3);
    h = make_uint2((uint32_t)hb0 | ((uint32_t)hb1 << 16),
                   (uint32_t)hb2 | ((uint32_t)hb3 << 16));
    m = make_uint2((uint32_t)m0 | ((uint32_t)m1 << 16),
                   (uint32_t)m2 | ((uint32_t)m3 << 16));
}

// ---------------------------------------------------------------------------
// Split kernel: x -> (hi = bf16(x), mid = bf16(x - hi)), packed 2x bf16/u32
// ---------------------------------------------------------------------------
__global__ __launch_bounds__(256) void split_bf16_kernel(
    const float4* __restrict__ src, uint2* __restrict__ hi,
    uint2* __restrict__ mid, int n4)
{
    int i = blockIdx.x * 256 + threadIdx.x;
    if (i >= n4) return;
    uint2 h, m;
    split4(src[i], h, m);
    hi[i] = h; mid[i] = m;
}

// ---------------------------------------------------------------------------
// bf16x3 GEMM via mma.sync (unchanged from R15 passing version)
// ---------------------------------------------------------------------------
#define BKE   32
#define RS    40
#define TILE_E (128*RS)
#define TILE_B (TILE_E*2)
#define STAGE_E (4*TILE_E)
#define STAGE_B (4*TILE_B)        // 40960 bytes
#define G_SMEM (2*STAGE_B)        // 81920 bytes -> 2 CTAs/SM
#define NCHUNK (1024/BKE)

template<int MODE>
__global__ __launch_bounds__(256, 2)
void tc_gemm(const __nv_bfloat16* __restrict__ Ah, const __nv_bfloat16* __restrict__ Am,
             const __nv_bfloat16* __restrict__ Bh, const __nv_bfloat16* __restrict__ Bm,
             const float* __restrict__ bias, float* __restrict__ Cout)
{
    extern __shared__ __nv_bfloat16 smbf[];
    const int tid  = threadIdx.x;
    const int wid  = tid >> 5;
    const int lane = tid & 31;
    const int m0 = blockIdx.y * 128;
    const int n0 = blockIdx.x * 128;
    const int warp_m = (wid & 1) * 64;
    const int warp_n = (wid >> 1) * 32;
    const int lr = lane >> 2;
    const int lc = lane & 3;

    const int g8 = lane >> 3, l8 = lane & 7;
    const int aoff = ((g8 & 1) * 8 + l8) * RS + (g8 >> 1) * 8;   // A m16k16
    const int boff = ((g8 >> 1) * 8 + l8) * RS + (g8 & 1) * 8;   // B n16k16

    float acc[4][4][4];
    #pragma unroll
    for (int mt = 0; mt < 4; mt++)
        #pragma unroll
        for (int nt = 0; nt < 4; nt++)
            #pragma unroll
            for (int r = 0; r < 4; r++) acc[mt][nt][r] = 0.0f;

    const uint32_t smb = smem_u32(smbf);

    auto load_chunk = [&](int st, int k0) {
        const uint32_t sb = smb + (uint32_t)st * STAGE_B;
        #pragma unroll
        for (int i = 0; i < 2; i++) {
            const int idx = tid + i * 256;
            const int r = idx >> 2, q = idx & 3;
            const uint32_t o = (uint32_t)r * (RS * 2) + (uint32_t)q * 16;
            const size_t ga = (size_t)(m0 + r) * 1024 + k0 + q * 8;
            const size_t gb = (size_t)(n0 + r) * 1024 + k0 + q * 8;
            cp16(sb + 0 * TILE_B + o, Ah + ga);
            cp16(sb + 1 * TILE_B + o, Am + ga);
            cp16(sb + 2 * TILE_B + o, Bh + gb);
            cp16(sb + 3 * TILE_B + o, Bm + gb);
        }
        asm volatile("cp.async.commit_group;" ::: "memory");
    };

    load_chunk(0, 0);
    load_chunk(1, BKE);

    for (int c = 0; c < NCHUNK; c++) {
        if (c < NCHUNK - 1) asm volatile("cp.async.wait_group 1;" ::: "memory");
        else                asm volatile("cp.async.wait_group 0;" ::: "memory");
        __syncthreads();

        const uint32_t sA_h = smb + (uint32_t)(c & 1) * STAGE_B;
        const uint32_t sA_m = sA_h + TILE_B;
        const uint32_t sB_h = sA_h + 2 * TILE_B;
        const uint32_t sB_m = sA_h + 3 * TILE_B;

        #pragma unroll
        for (int ks = 0; ks < 2; ks++) {
            const int k0 = ks * 16;
            uint32_t bh[2][4], bm[2][4];
            #pragma unroll
            for (int nb = 0; nb < 2; nb++) {
                const uint32_t off = 2u * ((uint32_t)(warp_n + nb * 16) * RS + k0 + boff);
                ldsm_x4(bh[nb], sB_h + off);
                ldsm_x4(bm[nb], sB_m + off);
            }
            #pragma unroll
            for (int mt = 0; mt < 4; mt++) {
                uint32_t ah4[4], am4[4];
                const uint32_t off = 2u * ((uint32_t)(warp_m + mt * 16) * RS + k0 + aoff);
                ldsm_x4(ah4, sA_h + off);
                ldsm_x4(am4, sA_m + off);
                #pragma unroll
                for (int nt = 0; nt < 4; nt++) {
                    const uint32_t* bbh = &bh[nt >> 1][(nt & 1) * 2];
                    const uint32_t* bbm = &bm[nt >> 1][(nt & 1) * 2];
                    mma16(acc[mt][nt], ah4, bbh);
                    mma16(acc[mt][nt], ah4, bbm);
                    mma16(acc[mt][nt], am4, bbh);
                }
            }
        }
        __syncthreads();
        if (c + 2 < NCHUNK) load_chunk(c & 1, (c + 2) * BKE);
    }

    // ---- Epilogue ----
    #pragma unroll
    for (int mt = 0; mt < 4; mt++) {
        #pragma unroll
        for (int nt = 0; nt < 4; nt++) {
            const int gm = m0 + warp_m + mt * 16 + lr;
            const int gn = n0 + warp_n + nt * 8 + lc * 2;
            #pragma unroll
            for (int half = 0; half < 2; half++) {
                const int m = gm + half * 8;
                float v0 = acc[mt][nt][half * 2 + 0] + __ldg(&bias[gn]);
                float v1 = acc[mt][nt][half * 2 + 1] + __ldg(&bias[gn + 1]);
                if (MODE == 0) {
                    const int s = m >> 3;
                    const int b = m & 7;
                    const int h = gn / 192;
                    const int cc = gn - h * 192;
                    const int w = cc >> 6;
                    const int d = cc & 63;
                    const size_t idx = ((size_t)(b * NH + h) * SEQ + s) * HD + d;
                    if (w == 0) { v0 *= 0.125f; v1 *= 0.125f; }
                    uint16_t h0, h1;
                    const float hv0 = bf16_val(v0, h0);
                    const float hv1 = bf16_val(v1, h1);
                    const uint32_t hh = (uint32_t)h0 | ((uint32_t)h1 << 16);
                    const uint32_t mm = (uint32_t)bf16_bits(v0 - hv0)
                                      | ((uint32_t)bf16_bits(v1 - hv1) << 16);
                    if (w == 0)      { *(uint32_t*)&g_Qh[idx] = hh; *(uint32_t*)&g_Qm[idx] = mm; }
                    else if (w == 1) { *(uint32_t*)&g_Kh[idx] = hh; *(uint32_t*)&g_Km[idx] = mm; }
                    else             { *(uint32_t*)&g_Vh[idx] = hh; *(uint32_t*)&g_Vm[idx] = mm; }
                } else {
                    Cout[(size_t)m * 1024 + gn]     = v0;
                    Cout[(size_t)m * 1024 + gn + 1] = v1;
                }
            }
        }
    }
}

// ---------------------------------------------------------------------------
// FA2-style bf16x3 flash attention. Block = (128 queries, head), 256 thr.
// 8 warps, each owns 16 q-rows x ALL 64 keys: softmax entirely in registers,
// P stays in registers (S-accum fragment layout == PV A-operand layout).
// K/V double-buffered cp.async; 2 barriers per k-tile.
// ---------------------------------------------------------------------------
#define ARS 72
#define PLANE_E (64*ARS)          // 4608 bf16 = 9216 B per plane
#define ATTN4_SMEM (8*PLANE_E*2)  // 2 bufs x 4 planes = 73728 B

__global__ __launch_bounds__(256, 1) void attn_tc_kernel()
{
    extern __shared__ __nv_bfloat16 shb[];
    const int tid  = threadIdx.x;
    const int wid  = tid >> 5;
    const int lane = tid & 31;
    const int lr = lane >> 2;
    const int lc = lane & 3;
    const int n  = blockIdx.y;           // head (b*16+h)
    const int qt = blockIdx.x;           // 128-query tile
    const int warp_m = wid * 16;

    const size_t headBase = (size_t)n * SEQ * HD;
    const size_t qBase = headBase + (size_t)qt * 128 * HD;

    const int g8 = lane >> 3, l8 = lane & 7;
    const int aoff = ((g8 & 1) * 8 + l8) * ARS + (g8 >> 1) * 8;   // A (Q)
    const int boff = ((g8 >> 1) * 8 + l8) * ARS + (g8 & 1) * 8;   // B (K)
    const int voff = ((g8 & 1) * 8 + l8) * ARS + (g8 >> 1) * 8;   // V (trans)

    const uint32_t base = smem_u32(shb);
    auto plane = [&](int buf, int p) -> uint32_t {
        return base + (uint32_t)((buf * 4 + p) * (PLANE_E * 2));
    };

    // ---- Stage Q (128 rows) into buf0's 4 plane slots, hoist to regs ----
    #pragma unroll
    for (int i = 0; i < 4; i++) {
        const int idx = tid + i * 256;
        const int r = idx >> 3, q = idx & 7;      // r 0..127
        const uint32_t o2 = (uint32_t)(r & 63) * (ARS * 2) + (uint32_t)q * 16;
        const int pl = r >> 6;
        const size_t go = qBase + (size_t)r * HD + q * 8;
        cp16(plane(0, pl)     + o2, g_Qh + go);
        cp16(plane(0, 2 + pl) + o2, g_Qm + go);
    }
    asm volatile("cp.async.commit_group;" ::: "memory");
    asm volatile("cp.async.wait_group 0;" ::: "memory");
    __syncthreads();

    uint32_t qh[4][4], qm[4][4];
    {
        const int qpl = warp_m >> 6;
        const int rm  = warp_m & 63;
        #pragma unroll
        for (int ks = 0; ks < 4; ks++) {
            const uint32_t off = 2u * ((uint32_t)rm * ARS + ks * 16 + aoff);
            ldsm_x4(qh[ks], plane(0, qpl)     + off);
            ldsm_x4(qm[ks], plane(0, 2 + qpl) + off);
        }
    }
    __syncthreads();   // Q consumed; buf0 reusable

    auto stageKV = [&](int kt, int buf) {
        #pragma unroll
        for (int i = 0; i < 2; i++) {
            const int idx = tid + i * 256;
            const int r = idx >> 3, q = idx & 7;  // r 0..63
            const uint32_t o2 = (uint32_t)r * (ARS * 2) + (uint32_t)q * 16;
            const size_t go = headBase + (size_t)(kt * 64 + r) * HD + q * 8;
            cp16(plane(buf, 0) + o2, g_Kh + go);
            cp16(plane(buf, 1) + o2, g_Km + go);
            cp16(plane(buf, 2) + o2, g_Vh + go);
            cp16(plane(buf, 3) + o2, g_Vm + go);
        }
        asm volatile("cp.async.commit_group;" ::: "memory");
    };

    stageKV(0, 0);

    float o[8][4];
    #pragma unroll
    for (int nt = 0; nt < 8; nt++)
        #pragma unroll
        for (int r = 0; r < 4; r++) o[nt][r] = 0.f;
    float mrun0 = -CUDART_INF_F, mrun1 = -CUDART_INF_F;
    float lrun0 = 0.f, lrun1 = 0.f;

    for (int kt = 0; kt < 16; kt++) {
        const int buf = kt & 1;
        if (kt + 1 < 16) stageKV(kt + 1, (kt + 1) & 1);
        if (kt + 1 < 16) asm volatile("cp.async.wait_group 1;" ::: "memory");
        else             asm volatile("cp.async.wait_group 0;" ::: "memory");
        __syncthreads();

        // ---- S = Q @ K^T (bf16x3), warp covers all 64 keys ----
        float s[8][4];
        #pragma unroll
        for (int nt = 0; nt < 8; nt++)
            #pragma unroll
            for (int r = 0; r < 4; r++) s[nt][r] = 0.f;

        #pragma unroll
        for (int ks = 0; ks < 4; ks++) {
            #pragma unroll
            for (int nb = 0; nb < 4; nb++) {
                uint32_t kh4[4], km4[4];
                const uint32_t off = 2u * ((uint32_t)(nb * 16) * ARS + ks * 16 + boff);
                ldsm_x4(kh4, plane(buf, 0) + off);
                ldsm_x4(km4, plane(buf, 1) + off);
                #pragma unroll
                for (int half = 0; half < 2; half++) {
                    float* st = s[nb * 2 + half];
                    mma16(st, qh[ks], &kh4[half * 2]);
                    mma16(st, qh[ks], &km4[half * 2]);
                    mma16(st, qm[ks], &kh4[half * 2]);
                }
            }
        }

        // ---- register softmax (rows lr and lr+8) ----
        float rmax0 = s[0][0], rmax1 = s[0][2];
        #pragma unroll
        for (int nt = 0; nt < 8; nt++) {
            rmax0 = fmaxf(rmax0, fmaxf(s[nt][0], s[nt][1]));
            rmax1 = fmaxf(rmax1, fmaxf(s[nt][2], s[nt][3]));
        }
        rmax0 = fmaxf(rmax0, __shfl_xor_sync(0xffffffffu, rmax0, 1));
        rmax0 = fmaxf(rmax0, __shfl_xor_sync(0xffffffffu, rmax0, 2));
        rmax1 = fmaxf(rmax1, __shfl_xor_sync(0xffffffffu, rmax1, 1));
        rmax1 = fmaxf(rmax1, __shfl_xor_sync(0xffffffffu, rmax1, 2));

        const float mnew0 = fmaxf(mrun0, rmax0);
        const float mnew1 = fmaxf(mrun1, rmax1);
        const float sc0 = __expf(mrun0 - mnew0);
        const float sc1 = __expf(mrun1 - mnew1);
        mrun0 = mnew0; mrun1 = mnew1;

        // ---- P = exp(S-m) -> register bf16 hi/mid A-fragments ----
        uint32_t ph4[4][4], pm4[4][4];
        float ps0 = 0.f, ps1 = 0.f;
        #pragma unroll
        for (int j = 0; j < 4; j++) {
            #pragma unroll
            for (int half = 0; half < 2; half++) {
                const float* st = s[j * 2 + half];
                const float e0 = __expf(st[0] - mnew0);
                const float e1 = __expf(st[1] - mnew0);
                const float e2 = __expf(st[2] - mnew1);
                const float e3 = __expf(st[3] - mnew1);
                ps0 += e0 + e1; ps1 += e2 + e3;
                uint16_t b0, b1, b2, b3;
                const float h0 = bf16_val(e0, b0);
                const float h1 = bf16_val(e1, b1);
                const float h2 = bf16_val(e2, b2);
                const float h3 = bf16_val(e3, b3);
                ph4[j][half * 2 + 0] = (uint32_t)b0 | ((uint32_t)b1 << 16);  // wait: order
                ph4[j][half * 2 + 1] = (uint32_t)b2 | ((uint32_t)b3 << 16);
                pm4[j][half * 2 + 0] = pack_bf16(e0 - h0, e1 - h1);
                pm4[j][half * 2 + 1] = pack_bf16(e2 - h2, e3 - h3);
            }
            // reorder to A-fragment convention: a0=row lr k-lo, a1=row lr+8 k-lo,
            // a2=row lr k-hi, a3=row lr+8 k-hi  (current: [0]=t0 rows lr, [1]=t0 lr+8,
            // [2]=t1 lr, [3]=t1 lr+8 — already matches a0..a3)
        }
        ps0 += __shfl_xor_sync(0xffffffffu, ps0, 1);
        ps0 += __shfl_xor_sync(0xffffffffu, ps0, 2);
        ps1 += __shfl_xor_sync(0xffffffffu, ps1, 1);
        ps1 += __shfl_xor_sync(0xffffffffu, ps1, 2);
        lrun0 = lrun0 * sc0 + ps0;
        lrun1 = lrun1 * sc1 + ps1;

        #pragma unroll
        for (int nt = 0; nt < 8; nt++) {
            o[nt][0] *= sc0; o[nt][1] *= sc0;
            o[nt][2] *= sc1; o[nt][3] *= sc1;
        }

        // ---- O += P @ V (bf16x3; V via ldmatrix.trans) ----
        #pragma unroll
        for (int ks = 0; ks < 4; ks++) {
            #pragma unroll
            for (int nb = 0; nb < 4; nb++) {
                uint32_t vh4[4], vm4[4];
                const uint32_t off = 2u * ((uint32_t)(ks * 16) * ARS + nb * 16 + voff);
                ldsm_x4_t(vh4, plane(buf, 2) + off);
                ldsm_x4_t(vm4, plane(buf, 3) + off);
                #pragma unroll
                for (int half = 0; half < 2; half++) {
                    float* ot = o[nb * 2 + half];
                    mma16(ot, ph4[ks], &vh4[half * 2]);
                    mma16(ot, ph4[ks], &vm4[half * 2]);
                    mma16(ot, pm4[ks], &vh4[half * 2]);
                }
            }
        }
        __syncthreads();   // all reads of buf done before it is restaged
    }

    // ---- Normalize and store ctx bf16 hi/mid splits to [s,b,e] ----
    const int b = n >> 4;
    const int h = n & 15;
    const float li0 = 1.0f / lrun0;
    const float li1 = 1.0f / lrun1;
    #pragma unroll
    for (int nt = 0; nt < 8; nt++) {
        const int d = nt * 8 + 2 * lc;
        #pragma unroll
        for (int half = 0; half < 2; half++) {
            const int row = qt * 128 + warp_m + lr + half * 8;
            const float li = half ? li1 : li0;
            const float v0 = o[nt][half * 2 + 0] * li;
            const float v1 = o[nt][half * 2 + 1] * li;
            const size_t addr = ((size_t)row * BATCH + b) * EMB + h * HD + d;
            uint16_t h0, h1;
            const float hv0 = bf16_val(v0, h0);
            const float hv1 = bf16_val(v1, h1);
            *(uint32_t*)&g_Ch[addr] = (uint32_t)h0 | ((uint32_t)h1 << 16);
            *(uint32_t*)&g_Cm[addr] =
                (uint32_t)bf16_bits(v0 - hv0) | ((uint32_t)bf16_bits(v1 - hv1) << 16);
        }
    }
}

// ---------------------------------------------------------------------------
extern "C" void kernel_launch(void* const* d_in, const int* in_sizes, int n_in,
                              void* d_out, int out_size)
{
    const float* X  = (const float*)d_in[0];  // query [S,B,E]
    const float* Wq = (const float*)d_in[3];  // in_proj_w [3E,E]
    const float* bq = (const float*)d_in[4];  // in_proj_b [3E]
    const float* Wo = (const float*)d_in[5];  // out_proj_w [E,E]
    const float* bo = (const float*)d_in[6];  // out_proj_b [E]
    float* out = (float*)d_out;

    cudaFuncSetAttribute(attn_tc_kernel,
                         cudaFuncAttributeMaxDynamicSharedMemorySize, ATTN4_SMEM);
    cudaFuncSetAttribute(tc_gemm<0>,
                         cudaFuncAttributeMaxDynamicSharedMemorySize, G_SMEM);
    cudaFuncSetAttribute(tc_gemm<1>,
                         cudaFuncAttributeMaxDynamicSharedMemorySize, G_SMEM);

    __nv_bfloat16 *xh, *xm, *wqh, *wqm, *woh, *wom, *ch, *cm;
    cudaGetSymbolAddress((void**)&xh,  g_Xh);
    cudaGetSymbolAddress((void**)&xm,  g_Xm);
    cudaGetSymbolAddress((void**)&wqh, g_Wqh);
    cudaGetSymbolAddress((void**)&wqm, g_Wqm);
    cudaGetSymbolAddress((void**)&woh, g_Woh);
    cudaGetSymbolAddress((void**)&wom, g_Wom);
    cudaGetSymbolAddress((void**)&ch,  g_Ch);
    cudaGetSymbolAddress((void**)&cm,  g_Cm);

    // 0) bf16 hi/mid splits of inputs and weights
    split_bf16_kernel<<<(MROWS*EMB/4 + 255)/256, 256>>>(
        (const float4*)X, (uint2*)xh, (uint2*)xm, MROWS*EMB/4);
    split_bf16_kernel<<<(3*EMB*EMB/4 + 255)/256, 256>>>(
        (const float4*)Wq, (uint2*)wqh, (uint2*)wqm, 3*EMB*EMB/4);
    split_bf16_kernel<<<(EMB*EMB/4 + 255)/256, 256>>>(
        (const float4*)Wo, (uint2*)woh, (uint2*)wom, EMB*EMB/4);

    // 1) QKV projection (bf16x3, ldmatrix, 2 CTAs/SM) + split-scatter to planes
    tc_gemm<0><<<dim3(3072/128, MROWS/128), 256, G_SMEM>>>(xh, xm, wqh, wqm, bq, nullptr);

    // 2) FA2-style bf16x3 flash attention (register softmax, register P)
    attn_tc_kernel<<<dim3(SEQ/128, NHEADS_TOT), 256, ATTN4_SMEM>>>();

    // 3) Output projection (bf16x3, ldmatrix, 2 CTAs/SM)
    tc_gemm<1><<<dim3(1024/128, MROWS/128), 256, G_SMEM>>>(ch, cm, woh, wom, bo, out);
}

// round 17
// speedup vs baseline: 1.4136x; 1.0182x over previous
#include <cuda_runtime.h>
#include <cuda_bf16.h>
#include <math_constants.h>
#include <cstdint>

// Problem constants
#define SEQ   1024
#define BATCH 8
#define EMB   1024
#define NH    16
#define HD    64
#define MROWS (SEQ*BATCH)        // 8192
#define NHEADS_TOT (BATCH*NH)    // 128
#define NSH   (NHEADS_TOT*SEQ*HD)

// ---------------------------------------------------------------------------
// Scratch (device globals; allocation-free). Q/K/V stored as bf16 hi/mid
// plane pairs in [n][s][d] layout (split once in tc_gemm<0> epilogue).
// ---------------------------------------------------------------------------
__device__ __nv_bfloat16 g_Qh[NSH], g_Qm[NSH];
__device__ __nv_bfloat16 g_Kh[NSH], g_Km[NSH];
__device__ __nv_bfloat16 g_Vh[NSH], g_Vm[NSH];
__device__ __nv_bfloat16 g_Xh[MROWS * EMB];
__device__ __nv_bfloat16 g_Xm[MROWS * EMB];
__device__ __nv_bfloat16 g_Wqh[3 * EMB * EMB];
__device__ __nv_bfloat16 g_Wqm[3 * EMB * EMB];
__device__ __nv_bfloat16 g_Woh[EMB * EMB];
__device__ __nv_bfloat16 g_Wom[EMB * EMB];
__device__ __nv_bfloat16 g_Ch[MROWS * EMB];    // ctx hi split, [s,b,e]
__device__ __nv_bfloat16 g_Cm[MROWS * EMB];    // ctx mid split

// ---------------------------------------------------------------------------
// Helpers (sm_103 plain: mma.sync + cp.async + ldmatrix only)
// ---------------------------------------------------------------------------
__device__ __forceinline__ uint32_t smem_u32(const void* p) {
    uint32_t a;
    asm("{ .reg .u64 t; cvta.to.shared.u64 t, %1; cvt.u32.u64 %0, t; }"
        : "=r"(a) : "l"(p));
    return a;
}

__device__ __forceinline__ void cp16(uint32_t dst, const void* src) {
    asm volatile("cp.async.cg.shared.global [%0], [%1], 16;" :: "r"(dst), "l"(src));
}

__device__ __forceinline__ uint16_t bf16_bits(float x) {
    return __bfloat16_as_ushort(__float2bfloat16(x));
}
__device__ __forceinline__ float bf16_val(float x, uint16_t& bits) {
    __nv_bfloat16 h = __float2bfloat16(x);
    bits = __bfloat16_as_ushort(h);
    return __bfloat162float(h);
}
__device__ __forceinline__ uint32_t pack_bf16(float a, float b) {
    return (uint32_t)bf16_bits(a) | ((uint32_t)bf16_bits(b) << 16);
}

// bf16 MMA: D += A(16x16) * B(16x8)^T
__device__ __forceinline__ void mma16(float* c, const uint32_t* a, const uint32_t* b) {
    asm volatile(
        "mma.sync.aligned.m16n8k16.row.col.f32.bf16.bf16.f32 "
        "{%0,%1,%2,%3}, {%4,%5,%6,%7}, {%8,%9}, {%0,%1,%2,%3};"
        : "+f"(c[0]), "+f"(c[1]), "+f"(c[2]), "+f"(c[3])
        : "r"(a[0]), "r"(a[1]), "r"(a[2]), "r"(a[3]), "r"(b[0]), "r"(b[1]));
}

__device__ __forceinline__ void ldsm_x4(uint32_t* r, uint32_t addr) {
    asm volatile("ldmatrix.sync.aligned.m8n8.x4.shared.b16 {%0,%1,%2,%3}, [%4];"
        : "=r"(r[0]), "=r"(r[1]), "=r"(r[2]), "=r"(r[3]) : "r"(addr));
}
__device__ __forceinline__ void ldsm_x4_t(uint32_t* r, uint32_t addr) {
    asm volatile("ldmatrix.sync.aligned.m8n8.x4.trans.shared.b16 {%0,%1,%2,%3}, [%4];"
        : "=r"(r[0]), "=r"(r[1]), "=r"(r[2]), "=r"(r[3]) : "r"(addr));
}

// float4 -> packed bf16 hi / mid uint2
__device__ __forceinline__ void split4(float4 v, uint2& h, uint2& m) {
    uint16_t hb0, hb1, hb2, hb3;
    float h0 = bf16_val(v.x, hb0);
    float h1 = bf16_val(v.y, hb1);
    float h2 = bf16_val(v.z, hb2);
    float h3 = bf16_val(v.w, hb3);
    uint16_t m0 = bf16_bits(v.x - h0), m1 = bf16_bits(v.y - h1);
    uint16_t m2 = bf16_bits(v.z - h2), m3 = bf16_bits(v.w - h3);
    h = make_uint2((uint32_t)hb0 | ((uint32_t)hb1 << 16),
                   (uint32_t)hb2 | ((uint32_t)hb3 << 16));
    m = make_uint2((uint32_t)m0 | ((uint32_t)m1 << 16),
                   (uint32_t)m2 | ((uint32_t)m3 << 16));
}

// ---------------------------------------------------------------------------
// Split kernel: x -> (hi = bf16(x), mid = bf16(x - hi)), packed 2x bf16/u32
// ---------------------------------------------------------------------------
__global__ __launch_bounds__(256) void split_bf16_kernel(
    const float4* __restrict__ src, uint2* __restrict__ hi,
    uint2* __restrict__ mid, int n4)
{
    int i = blockIdx.x * 256 + threadIdx.x;
    if (i >= n4) return;
    uint2 h, m;
    split4(src[i], h, m);
    hi[i] = h; mid[i] = m;
}

// ---------------------------------------------------------------------------
// bf16x3 GEMM via mma.sync (unchanged from R15/R16 passing version)
// ---------------------------------------------------------------------------
#define BKE   32
#define RS    40
#define TILE_E (128*RS)
#define TILE_B (TILE_E*2)
#define STAGE_E (4*TILE_E)
#define STAGE_B (4*TILE_B)        // 40960 bytes
#define G_SMEM (2*STAGE_B)        // 81920 bytes -> 2 CTAs/SM
#define NCHUNK (1024/BKE)

template<int MODE>
__global__ __launch_bounds__(256, 2)
void tc_gemm(const __nv_bfloat16* __restrict__ Ah, const __nv_bfloat16* __restrict__ Am,
             const __nv_bfloat16* __restrict__ Bh, const __nv_bfloat16* __restrict__ Bm,
             const float* __restrict__ bias, float* __restrict__ Cout)
{
    extern __shared__ __nv_bfloat16 smbf[];
    const int tid  = threadIdx.x;
    const int wid  = tid >> 5;
    const int lane = tid & 31;
    const int m0 = blockIdx.y * 128;
    const int n0 = blockIdx.x * 128;
    const int warp_m = (wid & 1) * 64;
    const int warp_n = (wid >> 1) * 32;
    const int lr = lane >> 2;
    const int lc = lane & 3;

    const int g8 = lane >> 3, l8 = lane & 7;
    const int aoff = ((g8 & 1) * 8 + l8) * RS + (g8 >> 1) * 8;   // A m16k16
    const int boff = ((g8 >> 1) * 8 + l8) * RS + (g8 & 1) * 8;   // B n16k16

    float acc[4][4][4];
    #pragma unroll
    for (int mt = 0; mt < 4; mt++)
        #pragma unroll
        for (int nt = 0; nt < 4; nt++)
            #pragma unroll
            for (int r = 0; r < 4; r++) acc[mt][nt][r] = 0.0f;

    const uint32_t smb = smem_u32(smbf);

    auto load_chunk = [&](int st, int k0) {
        const uint32_t sb = smb + (uint32_t)st * STAGE_B;
        #pragma unroll
        for (int i = 0; i < 2; i++) {
            const int idx = tid + i * 256;
            const int r = idx >> 2, q = idx & 3;
            const uint32_t o = (uint32_t)r * (RS * 2) + (uint32_t)q * 16;
            const size_t ga = (size_t)(m0 + r) * 1024 + k0 + q * 8;
            const size_t gb = (size_t)(n0 + r) * 1024 + k0 + q * 8;
            cp16(sb + 0 * TILE_B + o, Ah + ga);
            cp16(sb + 1 * TILE_B + o, Am + ga);
            cp16(sb + 2 * TILE_B + o, Bh + gb);
            cp16(sb + 3 * TILE_B + o, Bm + gb);
        }
        asm volatile("cp.async.commit_group;" ::: "memory");
    };

    load_chunk(0, 0);
    load_chunk(1, BKE);

    for (int c = 0; c < NCHUNK; c++) {
        if (c < NCHUNK - 1) asm volatile("cp.async.wait_group 1;" ::: "memory");
        else                asm volatile("cp.async.wait_group 0;" ::: "memory");
        __syncthreads();

        const uint32_t sA_h = smb + (uint32_t)(c & 1) * STAGE_B;
        const uint32_t sA_m = sA_h + TILE_B;
        const uint32_t sB_h = sA_h + 2 * TILE_B;
        const uint32_t sB_m = sA_h + 3 * TILE_B;

        #pragma unroll
        for (int ks = 0; ks < 2; ks++) {
            const int k0 = ks * 16;
            uint32_t bh[2][4], bm[2][4];
            #pragma unroll
            for (int nb = 0; nb < 2; nb++) {
                const uint32_t off = 2u * ((uint32_t)(warp_n + nb * 16) * RS + k0 + boff);
                ldsm_x4(bh[nb], sB_h + off);
                ldsm_x4(bm[nb], sB_m + off);
            }
            #pragma unroll
            for (int mt = 0; mt < 4; mt++) {
                uint32_t ah4[4], am4[4];
                const uint32_t off = 2u * ((uint32_t)(warp_m + mt * 16) * RS + k0 + aoff);
                ldsm_x4(ah4, sA_h + off);
                ldsm_x4(am4, sA_m + off);
                #pragma unroll
                for (int nt = 0; nt < 4; nt++) {
                    const uint32_t* bbh = &bh[nt >> 1][(nt & 1) * 2];
                    const uint32_t* bbm = &bm[nt >> 1][(nt & 1) * 2];
                    mma16(acc[mt][nt], ah4, bbh);
                    mma16(acc[mt][nt], ah4, bbm);
                    mma16(acc[mt][nt], am4, bbh);
                }
            }
        }
        __syncthreads();
        if (c + 2 < NCHUNK) load_chunk(c & 1, (c + 2) * BKE);
    }

    // ---- Epilogue ----
    #pragma unroll
    for (int mt = 0; mt < 4; mt++) {
        #pragma unroll
        for (int nt = 0; nt < 4; nt++) {
            const int gm = m0 + warp_m + mt * 16 + lr;
            const int gn = n0 + warp_n + nt * 8 + lc * 2;
            #pragma unroll
            for (int half = 0; half < 2; half++) {
                const int m = gm + half * 8;
                float v0 = acc[mt][nt][half * 2 + 0] + __ldg(&bias[gn]);
                float v1 = acc[mt][nt][half * 2 + 1] + __ldg(&bias[gn + 1]);
                if (MODE == 0) {
                    const int s = m >> 3;
                    const int b = m & 7;
                    const int h = gn / 192;
                    const int cc = gn - h * 192;
                    const int w = cc >> 6;
                    const int d = cc & 63;
                    const size_t idx = ((size_t)(b * NH + h) * SEQ + s) * HD + d;
                    if (w == 0) { v0 *= 0.125f; v1 *= 0.125f; }
                    uint16_t h0, h1;
                    const float hv0 = bf16_val(v0, h0);
                    const float hv1 = bf16_val(v1, h1);
                    const uint32_t hh = (uint32_t)h0 | ((uint32_t)h1 << 16);
                    const uint32_t mm = (uint32_t)bf16_bits(v0 - hv0)
                                      | ((uint32_t)bf16_bits(v1 - hv1) << 16);
                    if (w == 0)      { *(uint32_t*)&g_Qh[idx] = hh; *(uint32_t*)&g_Qm[idx] = mm; }
                    else if (w == 1) { *(uint32_t*)&g_Kh[idx] = hh; *(uint32_t*)&g_Km[idx] = mm; }
                    else             { *(uint32_t*)&g_Vh[idx] = hh; *(uint32_t*)&g_Vm[idx] = mm; }
                } else {
                    Cout[(size_t)m * 1024 + gn]     = v0;
                    Cout[(size_t)m * 1024 + gn + 1] = v1;
                }
            }
        }
    }
}

// ---------------------------------------------------------------------------
// FA2-style bf16x3 flash attention, high-occupancy variant.
// Block = 128 threads (4 warps), 64 queries x head; k-tiles of 32 keys.
// Warp owns 16 q-rows x ALL 32 keys: register softmax, register P.
// Smem: dedicated Q planes + double-buffered 32-row K/V planes = 55.3 KB
// -> 4 CTAs/SM. K/V cp.async double-buffered; 2 cheap 4-warp barriers/kt.
// ---------------------------------------------------------------------------
#define AQRS 72
#define QPLANE (64*AQRS)          // 4608 elems
#define KPLANE (32*AQRS)          // 2304 elems
#define ATTN5_SMEM ((2*QPLANE + 8*KPLANE) * 2)   // 55296 B

__global__ __launch_bounds__(128, 4) void attn_tc_kernel()
{
    extern __shared__ __nv_bfloat16 shb[];
    const int tid  = threadIdx.x;
    const int wid  = tid >> 5;
    const int lane = tid & 31;
    const int lr = lane >> 2;
    const int lc = lane & 3;
    const int n  = blockIdx.y;           // head (b*16+h)
    const int qt = blockIdx.x;           // 64-query tile
    const int warp_m = wid * 16;

    const size_t headBase = (size_t)n * SEQ * HD;
    const size_t qBase = headBase + (size_t)qt * 64 * HD;

    const int g8 = lane >> 3, l8 = lane & 7;
    const int aoff = ((g8 & 1) * 8 + l8) * AQRS + (g8 >> 1) * 8;   // A (Q)
    const int boff = ((g8 >> 1) * 8 + l8) * AQRS + (g8 & 1) * 8;   // B (K)
    const int voff = ((g8 & 1) * 8 + l8) * AQRS + (g8 >> 1) * 8;   // V (trans)

    const uint32_t base = smem_u32(shb);
    const uint32_t sQh = base;
    const uint32_t sQm = base + QPLANE * 2;
    auto kvplane = [&](int buf, int p) -> uint32_t {
        return base + (uint32_t)(2 * QPLANE * 2) + (uint32_t)((buf * 4 + p) * (KPLANE * 2));
    };

    // ---- Stage Q once (group 0) ----
    #pragma unroll
    for (int i = 0; i < 4; i++) {
        const int idx = tid + i * 128;
        const int r = idx >> 3, q = idx & 7;      // r 0..63
        const uint32_t o2 = (uint32_t)r * (AQRS * 2) + (uint32_t)q * 16;
        const size_t go = qBase + (size_t)r * HD + q * 8;
        cp16(sQh + o2, g_Qh + go);
        cp16(sQm + o2, g_Qm + go);
    }
    asm volatile("cp.async.commit_group;" ::: "memory");

    auto stageKV = [&](int kt, int buf) {
        #pragma unroll
        for (int i = 0; i < 2; i++) {
            const int idx = tid + i * 128;
            const int r = idx >> 3, q = idx & 7;  // r 0..31
            const uint32_t o2 = (uint32_t)r * (AQRS * 2) + (uint32_t)q * 16;
            const size_t go = headBase + (size_t)(kt * 32 + r) * HD + q * 8;
            cp16(kvplane(buf, 0) + o2, g_Kh + go);
            cp16(kvplane(buf, 1) + o2, g_Km + go);
            cp16(kvplane(buf, 2) + o2, g_Vh + go);
            cp16(kvplane(buf, 3) + o2, g_Vm + go);
        }
        asm volatile("cp.async.commit_group;" ::: "memory");
    };

    stageKV(0, 0);                                // group 1
    asm volatile("cp.async.wait_group 1;" ::: "memory");  // Q ready
    __syncthreads();

    // Hoist Q fragments (tile-invariant; Q planes are dedicated, never reused)
    uint32_t qh[4][4], qm[4][4];
    #pragma unroll
    for (int ks = 0; ks < 4; ks++) {
        const uint32_t off = 2u * ((uint32_t)warp_m * AQRS + ks * 16 + aoff);
        ldsm_x4(qh[ks], sQh + off);
        ldsm_x4(qm[ks], sQm + off);
    }

    float o[8][4];
    #pragma unroll
    for (int nt = 0; nt < 8; nt++)
        #pragma unroll
        for (int r = 0; r < 4; r++) o[nt][r] = 0.f;
    float mrun0 = -CUDART_INF_F, mrun1 = -CUDART_INF_F;
    float lrun0 = 0.f, lrun1 = 0.f;

    for (int kt = 0; kt < 32; kt++) {
        const int buf = kt & 1;
        if (kt + 1 < 32) stageKV(kt + 1, (kt + 1) & 1);
        if (kt + 1 < 32) asm volatile("cp.async.wait_group 1;" ::: "memory");
        else             asm volatile("cp.async.wait_group 0;" ::: "memory");
        __syncthreads();

        // ---- S = Q @ K^T (bf16x3), warp covers all 32 keys ----
        float s[4][4];
        #pragma unroll
        for (int nt = 0; nt < 4; nt++)
            #pragma unroll
            for (int r = 0; r < 4; r++) s[nt][r] = 0.f;

        #pragma unroll
        for (int ks = 0; ks < 4; ks++) {
            #pragma unroll
            for (int nb = 0; nb < 2; nb++) {
                uint32_t kh4[4], km4[4];
                const uint32_t off = 2u * ((uint32_t)(nb * 16) * AQRS + ks * 16 + boff);
                ldsm_x4(kh4, kvplane(buf, 0) + off);
                ldsm_x4(km4, kvplane(buf, 1) + off);
                #pragma unroll
                for (int half = 0; half < 2; half++) {
                    float* st = s[nb * 2 + half];
                    mma16(st, qh[ks], &kh4[half * 2]);
                    mma16(st, qh[ks], &km4[half * 2]);
                    mma16(st, qm[ks], &kh4[half * 2]);
                }
            }
        }

        // ---- register softmax (rows lr and lr+8) ----
        float rmax0 = s[0][0], rmax1 = s[0][2];
        #pragma unroll
        for (int nt = 0; nt < 4; nt++) {
            rmax0 = fmaxf(rmax0, fmaxf(s[nt][0], s[nt][1]));
            rmax1 = fmaxf(rmax1, fmaxf(s[nt][2], s[nt][3]));
        }
        rmax0 = fmaxf(rmax0, __shfl_xor_sync(0xffffffffu, rmax0, 1));
        rmax0 = fmaxf(rmax0, __shfl_xor_sync(0xffffffffu, rmax0, 2));
        rmax1 = fmaxf(rmax1, __shfl_xor_sync(0xffffffffu, rmax1, 1));
        rmax1 = fmaxf(rmax1, __shfl_xor_sync(0xffffffffu, rmax1, 2));

        const float mnew0 = fmaxf(mrun0, rmax0);
        const float mnew1 = fmaxf(mrun1, rmax1);
        const float sc0 = __expf(mrun0 - mnew0);
        const float sc1 = __expf(mrun1 - mnew1);
        mrun0 = mnew0; mrun1 = mnew1;

        // ---- P = exp(S-m) -> register bf16 hi/mid A-fragments ----
        uint32_t ph4[2][4], pm4[2][4];
        float ps0 = 0.f, ps1 = 0.f;
        #pragma unroll
        for (int j = 0; j < 2; j++) {
            #pragma unroll
            for (int half = 0; half < 2; half++) {
                const float* st = s[j * 2 + half];
                const float e0 = __expf(st[0] - mnew0);
                const float e1 = __expf(st[1] - mnew0);
                const float e2 = __expf(st[2] - mnew1);
                const float e3 = __expf(st[3] - mnew1);
                ps0 += e0 + e1; ps1 += e2 + e3;
                uint16_t b0, b1, b2, b3;
                const float h0 = bf16_val(e0, b0);
                const float h1 = bf16_val(e1, b1);
                const float h2 = bf16_val(e2, b2);
                const float h3 = bf16_val(e3, b3);
                ph4[j][half * 2 + 0] = (uint32_t)b0 | ((uint32_t)b1 << 16);
                ph4[j][half * 2 + 1] = (uint32_t)b2 | ((uint32_t)b3 << 16);
                pm4[j][half * 2 + 0] = pack_bf16(e0 - h0, e1 - h1);
                pm4[j][half * 2 + 1] = pack_bf16(e2 - h2, e3 - h3);
            }
        }
        ps0 += __shfl_xor_sync(0xffffffffu, ps0, 1);
        ps0 += __shfl_xor_sync(0xffffffffu, ps0, 2);
        ps1 += __shfl_xor_sync(0xffffffffu, ps1, 1);
        ps1 += __shfl_xor_sync(0xffffffffu, ps1, 2);
        lrun0 = lrun0 * sc0 + ps0;
        lrun1 = lrun1 * sc1 + ps1;

        #pragma unroll
        for (int nt = 0; nt < 8; nt++) {
            o[nt][0] *= sc0; o[nt][1] *= sc0;
            o[nt][2] *= sc1; o[nt][3] *= sc1;
        }

        // ---- O += P @ V (bf16x3; V via ldmatrix.trans) ----
        #pragma unroll
        for (int ks2 = 0; ks2 < 2; ks2++) {
            #pragma unroll
            for (int nb = 0; nb < 4; nb++) {
                uint32_t vh4[4], vm4[4];
                const uint32_t off = 2u * ((uint32_t)(ks2 * 16) * AQRS + nb * 16 + voff);
                ldsm_x4_t(vh4, kvplane(buf, 2) + off);
                ldsm_x4_t(vm4, kvplane(buf, 3) + off);
                #pragma unroll
                for (int half = 0; half < 2; half++) {
                    float* ot = o[nb * 2 + half];
                    mma16(ot, ph4[ks2], &vh4[half * 2]);
                    mma16(ot, ph4[ks2], &vm4[half * 2]);
                    mma16(ot, pm4[ks2], &vh4[half * 2]);
                }
            }
        }
        __syncthreads();   // all reads of buf done before it is restaged
    }

    // ---- Normalize and store ctx bf16 hi/mid splits to [s,b,e] ----
    const int b = n >> 4;
    const int h = n & 15;
    const float li0 = 1.0f / lrun0;
    const float li1 = 1.0f / lrun1;
    #pragma unroll
    for (int nt = 0; nt < 8; nt++) {
        const int d = nt * 8 + 2 * lc;
        #pragma unroll
        for (int half = 0; half < 2; half++) {
            const int row = qt * 64 + warp_m + lr + half * 8;
            const float li = half ? li1 : li0;
            const float v0 = o[nt][half * 2 + 0] * li;
            const float v1 = o[nt][half * 2 + 1] * li;
            const size_t addr = ((size_t)row * BATCH + b) * EMB + h * HD + d;
            uint16_t h0, h1;
            const float hv0 = bf16_val(v0, h0);
            const float hv1 = bf16_val(v1, h1);
            *(uint32_t*)&g_Ch[addr] = (uint32_t)h0 | ((uint32_t)h1 << 16);
            *(uint32_t*)&g_Cm[addr] =
                (uint32_t)bf16_bits(v0 - hv0) | ((uint32_t)bf16_bits(v1 - hv1) << 16);
        }
    }
}

// ---------------------------------------------------------------------------
extern "C" void kernel_launch(void* const* d_in, const int* in_sizes, int n_in,
                              void* d_out, int out_size)
{
    const float* X  = (const float*)d_in[0];  // query [S,B,E]
    const float* Wq = (const float*)d_in[3];  // in_proj_w [3E,E]
    const float* bq = (const float*)d_in[4];  // in_proj_b [3E]
    const float* Wo = (const float*)d_in[5];  // out_proj_w [E,E]
    const float* bo = (const float*)d_in[6];  // out_proj_b [E]
    float* out = (float*)d_out;

    cudaFuncSetAttribute(attn_tc_kernel,
                         cudaFuncAttributeMaxDynamicSharedMemorySize, ATTN5_SMEM);
    cudaFuncSetAttribute(tc_gemm<0>,
                         cudaFuncAttributeMaxDynamicSharedMemorySize, G_SMEM);
    cudaFuncSetAttribute(tc_gemm<1>,
                         cudaFuncAttributeMaxDynamicSharedMemorySize, G_SMEM);

    __nv_bfloat16 *xh, *xm, *wqh, *wqm, *woh, *wom, *ch, *cm;
    cudaGetSymbolAddress((void**)&xh,  g_Xh);
    cudaGetSymbolAddress((void**)&xm,  g_Xm);
    cudaGetSymbolAddress((void**)&wqh, g_Wqh);
    cudaGetSymbolAddress((void**)&wqm, g_Wqm);
    cudaGetSymbolAddress((void**)&woh, g_Woh);
    cudaGetSymbolAddress((void**)&wom, g_Wom);
    cudaGetSymbolAddress((void**)&ch,  g_Ch);
    cudaGetSymbolAddress((void**)&cm,  g_Cm);

    // 0) bf16 hi/mid splits of inputs and weights
    split_bf16_kernel<<<(MROWS*EMB/4 + 255)/256, 256>>>(
        (const float4*)X, (uint2*)xh, (uint2*)xm, MROWS*EMB/4);
    split_bf16_kernel<<<(3*EMB*EMB/4 + 255)/256, 256>>>(
        (const float4*)Wq, (uint2*)wqh, (uint2*)wqm, 3*EMB*EMB/4);
    split_bf16_kernel<<<(EMB*EMB/4 + 255)/256, 256>>>(
        (const float4*)Wo, (uint2*)woh, (uint2*)wom, EMB*EMB/4);

    // 1) QKV projection (bf16x3, ldmatrix, 2 CTAs/SM) + split-scatter to planes
    tc_gemm<0><<<dim3(3072/128, MROWS/128), 256, G_SMEM>>>(xh, xm, wqh, wqm, bq, nullptr);

    // 2) FA2-style bf16x3 flash attention (128 thr, 4 CTAs/SM)
    attn_tc_kernel<<<dim3(SEQ/64, NHEADS_TOT), 128, ATTN5_SMEM>>>();

    // 3) Output projection (bf16x3, ldmatrix, 2 CTAs/SM)
    tc_gemm<1><<<dim3(1024/128, MROWS/128), 256, G_SMEM>>>(ch, cm, woh, wom, bo, out);
}